// round 12
// baseline (speedup 1.0000x reference)
#include <cuda_runtime.h>
#include <cuda_bf16.h>
#include <math.h>

typedef __nv_bfloat16 bf16;

#define D_MODEL 192
#define D_STATE 16
#define D_CONV  4
#define D_INNER 384
#define DT_RANK 12
#define BB      4
#define NN      1024
#define NPAIR   16
#define ROWS    (BB*NN)
#define DBL_W   (DT_RANK + 2*D_STATE)
#define NCH     4
#define CL      (NN/NCH)          // 256

// ---------------- scratch ----------------
__device__ float g_XS [ROWS * D_MODEL];
__device__ float g_XZ [NPAIR * NN * 2 * D_INNER];
__device__ float g_XSM[NPAIR * NN * D_INNER];
__device__ float g_DBL[NPAIR * NN * DBL_W];
__device__ float g_DD [NPAIR * NN * D_INNER * 2];     // (dt, dt*x)
__device__ float g_SC [NPAIR * NN * D_INNER];         // cumulative sum of dt within chunk
__device__ float g_HST  [NPAIR * 3 * D_INNER * D_STATE];  // partial end states (chunks 0..2)
__device__ float g_HINIT[NPAIR * 3 * D_INNER * D_STATE];  // combined init states (chunks 1..3)
__device__ float g_Y  [NPAIR * NN * D_INNER];
__device__ float g_H3 [ROWS * D_MODEL];

__device__ bf16 g_win_h [D_MODEL*D_MODEL],     g_win_l [D_MODEL*D_MODEL];
__device__ bf16 g_wmin_h[4*2*D_INNER*D_MODEL], g_wmin_l[4*2*D_INNER*D_MODEL];
__device__ bf16 g_wmo_h [4*D_MODEL*D_INNER],   g_wmo_l [4*D_MODEL*D_INNER];
__device__ bf16 g_wf1_h [2*D_MODEL*4*D_MODEL], g_wf1_l [2*D_MODEL*4*D_MODEL];
__device__ bf16 g_wf2_h [D_MODEL*2*D_MODEL],   g_wf2_l [D_MODEL*2*D_MODEL];
__device__ bf16 g_wo_h  [D_MODEL*D_MODEL],     g_wo_l  [D_MODEL*D_MODEL];
__device__ bf16 g_XSh [ROWS*D_MODEL],     g_XSl [ROWS*D_MODEL];
__device__ bf16 g_XPh [ROWS*D_MODEL],     g_XPl [ROWS*D_MODEL];
__device__ bf16 g_YGh [NPAIR*NN*D_INNER], g_YGl [NPAIR*NN*D_INNER];
__device__ bf16 g_FUSh[ROWS*4*D_MODEL],   g_FUSl[ROWS*4*D_MODEL];
__device__ bf16 g_H1h [ROWS*2*D_MODEL],   g_H1l [ROWS*2*D_MODEL];
__device__ bf16 g_H2h [ROWS*D_MODEL],     g_H2l [ROWS*D_MODEL];

// ---------------- helpers ----------------
__device__ __forceinline__ float siluf(float x) { return x / (1.0f + expf(-x)); }

__device__ __forceinline__ int dirmap(int k, int t) {
    if (k == 0) return t;
    if (k == 1) return 1023 - t;
    if (k == 2) return ((t & 31) << 5) | (t >> 5);
    int tt = 1023 - t;
    return ((tt & 31) << 5) | (tt >> 5);
}

__device__ __forceinline__ void split_hl(float v, bf16& h, bf16& l) {
    h = __float2bfloat16(v);
    l = __float2bfloat16(v - __bfloat162float(h));
}

__device__ __forceinline__ void block_reduce2_192(float& a, float& b) {
    #pragma unroll
    for (int o = 16; o > 0; o >>= 1) {
        a += __shfl_xor_sync(0xffffffffu, a, o);
        b += __shfl_xor_sync(0xffffffffu, b, o);
    }
    __shared__ float sa[6], sb[6];
    int w = threadIdx.x >> 5, l = threadIdx.x & 31;
    if (l == 0) { sa[w] = a; sb[w] = b; }
    __syncthreads();
    if (threadIdx.x == 0) {
        float ta = 0.f, tb = 0.f;
        #pragma unroll
        for (int i = 0; i < 6; i++) { ta += sa[i]; tb += sb[i]; }
        sa[0] = ta; sb[0] = tb;
    }
    __syncthreads();
    a = sa[0]; b = sb[0];
}

__device__ __forceinline__ void ldsm4(unsigned& r0, unsigned& r1, unsigned& r2, unsigned& r3, unsigned addr) {
    asm volatile("ldmatrix.sync.aligned.m8n8.x4.shared.b16 {%0,%1,%2,%3}, [%4];"
                 : "=r"(r0), "=r"(r1), "=r"(r2), "=r"(r3) : "r"(addr));
}
__device__ __forceinline__ void mma16816(float* c, const unsigned* a, const unsigned* b) {
    asm volatile("mma.sync.aligned.m16n8k16.row.col.f32.bf16.bf16.f32 "
                 "{%0,%1,%2,%3}, {%4,%5,%6,%7}, {%8,%9}, {%0,%1,%2,%3};"
                 : "+f"(c[0]), "+f"(c[1]), "+f"(c[2]), "+f"(c[3])
                 : "r"(a[0]), "r"(a[1]), "r"(a[2]), "r"(a[3]), "r"(b[0]), "r"(b[1]));
}
__device__ __forceinline__ void cpasync16(unsigned dst, const void* src) {
    asm volatile("cp.async.cg.shared.global [%0], [%1], 16;\n" :: "r"(dst), "l"(src));
}
__device__ __forceinline__ void cp_commit() { asm volatile("cp.async.commit_group;\n" ::); }
__device__ __forceinline__ void cp_wait0()  { asm volatile("cp.async.wait_group 0;\n" ::); }

// ---------------- bf16 split tensor GEMM (2-stage, combined 3-product) ------
#define P_PITCH 40
#define AH_OFF  0
#define AL_OFF  10240
#define BH_OFF  20480
#define BL_OFF  25600
#define STG_B   30720
#define GEMM_SMEM (2*STG_B)

template<int DM, int SM>
__global__ __launch_bounds__(256, 3) void gemm_mma(
    const bf16* __restrict__ Ah, const bf16* __restrict__ Al,
    const bf16* __restrict__ Bh, const bf16* __restrict__ Bl,
    const float* __restrict__ bias,
    float* __restrict__ outF, bf16* __restrict__ oh, bf16* __restrict__ ol,
    int M, int N, int K, long sA, long sB, long sC, int bdiv, int act)
{
    extern __shared__ char dynsmem[];
    const unsigned smem0 = (unsigned)__cvta_generic_to_shared(dynsmem);

    const int t = threadIdx.x, lane = t & 31, w = t >> 5;
    const int wm = w & 3, wn = w >> 2;
    const int m0 = blockIdx.y * 128, n0 = blockIdx.x * 64;
    const int bz = blockIdx.z;
    const int kdir = bz >> 2;

    const bf16 *Abh, *Abl;
    if (DM == 1) { long o = (long)(bz & 3) * NN * K; Abh = Ah + o; Abl = Al + o; }
    else         { Abh = Ah + (long)bz * sA; Abl = Al + (long)bz * sA; }
    const bf16* Bbh = Bh + (long)(bz / bdiv) * sB;
    const bf16* Bbl = Bl + (long)(bz / bdiv) * sB;

    long aoff[2]; unsigned aswb[2];
    #pragma unroll
    for (int i = 0; i < 2; i++) {
        int u = t + i * 256, r = u >> 2, cu = u & 3;
        int rg = m0 + r;
        if (DM == 1) rg = dirmap(kdir, rg);
        aoff[i] = (long)rg * K + cu * 8;
        aswb[i] = (unsigned)((r * P_PITCH + cu * 8) * 2);
    }
    long boff; unsigned bswb;
    { int r = t >> 2, cu = t & 3;
      boff = (long)(n0 + r) * K + cu * 8;
      bswb = (unsigned)((r * P_PITCH + cu * 8) * 2); }

    const int KT = K >> 5;

    int arow[2], brow[2];
    #pragma unroll
    for (int mt = 0; mt < 2; mt++)
        arow[mt] = (wm * 32 + mt * 16 + (lane & 15)) * P_PITCH + ((lane >> 4) << 3);
    #pragma unroll
    for (int b2 = 0; b2 < 2; b2++)
        brow[b2] = (wn * 32 + b2 * 16 + (lane & 15)) * P_PITCH + ((lane >> 4) << 3);

    float acc[2][4][4] = {};

    auto issue = [&](int stg, int kt) {
        int k0 = kt << 5;
        unsigned sb = smem0 + (unsigned)(stg * STG_B);
        cpasync16(sb + AH_OFF + aswb[0], Abh + aoff[0] + k0);
        cpasync16(sb + AH_OFF + aswb[1], Abh + aoff[1] + k0);
        cpasync16(sb + AL_OFF + aswb[0], Abl + aoff[0] + k0);
        cpasync16(sb + AL_OFF + aswb[1], Abl + aoff[1] + k0);
        cpasync16(sb + BH_OFF + bswb,   Bbh + boff + k0);
        cpasync16(sb + BL_OFF + bswb,   Bbl + boff + k0);
    };

    issue(0, 0); cp_commit();

    for (int it = 0; it < KT; it++) {
        cp_wait0();
        __syncthreads();
        if (it + 1 < KT) { issue((it + 1) & 1, it + 1); cp_commit(); }
        unsigned base = smem0 + (unsigned)((it & 1) * STG_B);
        #pragma unroll
        for (int ks = 0; ks < 2; ks++) {
            unsigned ah[2][4], al[2][4], bh2[4][2], bl2[4][2];
            #pragma unroll
            for (int mt = 0; mt < 2; mt++)
                ldsm4(ah[mt][0], ah[mt][1], ah[mt][2], ah[mt][3],
                      base + AH_OFF + (unsigned)((arow[mt] + ks * 16) * 2));
            #pragma unroll
            for (int b2 = 0; b2 < 2; b2++) {
                unsigned r0, r1, r2, r3;
                ldsm4(r0, r1, r2, r3, base + BH_OFF + (unsigned)((brow[b2] + ks * 16) * 2));
                bh2[b2*2][0] = r0; bh2[b2*2+1][0] = r1;
                bh2[b2*2][1] = r2; bh2[b2*2+1][1] = r3;
            }
            #pragma unroll
            for (int mt = 0; mt < 2; mt++)
                #pragma unroll
                for (int nt = 0; nt < 4; nt++)
                    mma16816(acc[mt][nt], ah[mt], bh2[nt]);
            #pragma unroll
            for (int b2 = 0; b2 < 2; b2++) {
                unsigned r0, r1, r2, r3;
                ldsm4(r0, r1, r2, r3, base + BL_OFF + (unsigned)((brow[b2] + ks * 16) * 2));
                bl2[b2*2][0] = r0; bl2[b2*2+1][0] = r1;
                bl2[b2*2][1] = r2; bl2[b2*2+1][1] = r3;
            }
            #pragma unroll
            for (int mt = 0; mt < 2; mt++)
                #pragma unroll
                for (int nt = 0; nt < 4; nt++)
                    mma16816(acc[mt][nt], ah[mt], bl2[nt]);
            #pragma unroll
            for (int mt = 0; mt < 2; mt++)
                ldsm4(al[mt][0], al[mt][1], al[mt][2], al[mt][3],
                      base + AL_OFF + (unsigned)((arow[mt] + ks * 16) * 2));
            #pragma unroll
            for (int mt = 0; mt < 2; mt++)
                #pragma unroll
                for (int nt = 0; nt < 4; nt++)
                    mma16816(acc[mt][nt], al[mt], bh2[nt]);
        }
    }

    #pragma unroll
    for (int mt = 0; mt < 2; mt++)
    #pragma unroll
    for (int nt = 0; nt < 4; nt++) {
        int col = n0 + wn * 32 + nt * 8 + ((lane & 3) << 1);
        #pragma unroll
        for (int h = 0; h < 2; h++) {
            int rr = m0 + wm * 32 + mt * 16 + (lane >> 2) + h * 8;
            float v0 = acc[mt][nt][h*2+0], v1 = acc[mt][nt][h*2+1];
            if (bias) { v0 += bias[col]; v1 += bias[col+1]; }
            if (act) {
                v0 = 0.5f * v0 * (1.0f + erff(v0 * 0.70710678118654752f));
                v1 = 0.5f * v1 * (1.0f + erff(v1 * 0.70710678118654752f));
            }
            if (SM == 1) {
                int n = dirmap(kdir, rr);
                long o = ((long)((bz & 3) * NN + n)) * (4 * D_MODEL) + kdir * D_MODEL + col;
                __nv_bfloat162 hv, lv;
                split_hl(v0, hv.x, lv.x); split_hl(v1, hv.y, lv.y);
                *(__nv_bfloat162*)(oh + o) = hv;
                *(__nv_bfloat162*)(ol + o) = lv;
            } else if (outF) {
                *(float2*)(outF + (long)bz * sC + (long)rr * N + col) = make_float2(v0, v1);
            } else {
                long o = (long)rr * N + col;
                __nv_bfloat162 hv, lv;
                split_hl(v0, hv.x, lv.x); split_hl(v1, hv.y, lv.y);
                *(__nv_bfloat162*)(oh + o) = hv;
                *(__nv_bfloat162*)(ol + o) = lv;
            }
        }
    }
}

// ---------------- fp32 SIMT GEMM (x-proj, N=44) with B/C quad permute ------
// cols 0..11 (dt_low) unchanged; B_s/C_s interleaved so that floats
// [12+4j .. 12+4j+3] = (B_j, C_j, B_{j+8}, C_{j+8}).
__global__ __launch_bounds__(256) void gemm_abt(
    const float* __restrict__ A, const float* __restrict__ Bw,
    float* __restrict__ C, int M, int N, int K, long sA, long sB, long sC, int bdiv)
{
    int bz = blockIdx.z;
    const float* Ab = A + (long)bz * sA;
    const float* Bb = Bw + (long)(bz / bdiv) * sB;
    float* Cb = C + (long)bz * sC;
    __shared__ float As[16][64];
    __shared__ float Bs[16][64];
    int t = threadIdx.x;
    int tr = t >> 4, tc = t & 15;
    int m0 = blockIdx.y << 6, n0 = blockIdx.x << 6;
    int lm = t >> 2, lk = (t & 3) << 2;
    float acc[4][4] = {};
    int nK = K >> 4;
    for (int kb = 0; kb < nK; kb++) {
        int k0 = kb << 4;
        float4 av = make_float4(0.f,0.f,0.f,0.f), bv = make_float4(0.f,0.f,0.f,0.f);
        if (m0 + lm < M) av = *(const float4*)(Ab + (long)(m0 + lm) * K + k0 + lk);
        if (n0 + lm < N) bv = *(const float4*)(Bb + (long)(n0 + lm) * K + k0 + lk);
        __syncthreads();
        As[lk+0][lm]=av.x; As[lk+1][lm]=av.y; As[lk+2][lm]=av.z; As[lk+3][lm]=av.w;
        Bs[lk+0][lm]=bv.x; Bs[lk+1][lm]=bv.y; Bs[lk+2][lm]=bv.z; Bs[lk+3][lm]=bv.w;
        __syncthreads();
        #pragma unroll
        for (int kk = 0; kk < 16; kk++) {
            float4 a4 = *(const float4*)&As[kk][tr << 2];
            float4 b4 = *(const float4*)&Bs[kk][tc << 2];
            float ar[4] = {a4.x,a4.y,a4.z,a4.w}, br[4] = {b4.x,b4.y,b4.z,b4.w};
            #pragma unroll
            for (int i = 0; i < 4; i++)
                #pragma unroll
                for (int j = 0; j < 4; j++) acc[i][j] += ar[i] * br[j];
        }
    }
    #pragma unroll
    for (int i = 0; i < 4; i++) {
        int m = m0 + (tr << 2) + i;
        if (m >= M) continue;
        #pragma unroll
        for (int j = 0; j < 4; j++) {
            int n = n0 + (tc << 2) + j;
            if (n >= N) continue;
            int nw;
            if (n < 12) nw = n;
            else {
                int s = n - 12;
                if (s < 16) nw = 12 + 4 * (s & 7) + 2 * (s >> 3);
                else { int ss = s - 16; nw = 12 + 4 * (ss & 7) + 2 * (ss >> 3) + 1; }
            }
            Cb[(long)m * N + nw] = acc[i][j];
        }
    }
}

// ---------------- weight fp32 -> hi/lo ----------------
struct Seg { const float* s; bf16* h; bf16* l; int n; };
struct Segs { Seg a[6]; };
__global__ void wconv(Segs P) {
    Seg sg = P.a[blockIdx.y];
    int i = blockIdx.x * 256 + threadIdx.x;
    if (i < sg.n) { bf16 h, l; split_hl(sg.s[i], h, l); sg.h[i] = h; sg.l[i] = l; }
}

// ---------------- LN in ----------------
__global__ void ln_in_kernel(const float* __restrict__ x,
                             const float* __restrict__ g,
                             const float* __restrict__ b,
                             float* __restrict__ XS,
                             bf16* __restrict__ XSh, bf16* __restrict__ XSl) {
    int row = blockIdx.x;
    int bb = row >> 10, n = row & 1023;
    int c = threadIdx.x;
    float v = x[((long)bb * D_MODEL + c) * NN + n];
    float s = v, s2 = v * v;
    block_reduce2_192(s, s2);
    float mean = s * (1.0f / D_MODEL);
    float var = s2 * (1.0f / D_MODEL) - mean * mean;
    float rstd = rsqrtf(var + 1e-5f);
    float r = (v - mean) * rstd * g[c] + b[c];
    long o = (long)row * D_MODEL + c;
    XS[o] = r;
    bf16 h, l; split_hl(r, h, l);
    XSh[o] = h; XSl[o] = l;
}

// ---------------- conv + silu ----------------
__global__ void conv_silu_kernel(const float* __restrict__ XZ,
                                 const float* __restrict__ cw,
                                 const float* __restrict__ cb,
                                 float* __restrict__ XSM) {
    long idx = (long)blockIdx.x * blockDim.x + threadIdx.x;
    int d = (int)(idx % D_INNER);
    int t = (int)((idx / D_INNER) & 1023);
    int gp = (int)(idx / ((long)D_INNER * NN));
    int k = gp >> 2;
    const float* base = XZ + ((long)gp * NN) * (2 * D_INNER) + d;
    const float* w = cw + ((long)k * D_INNER + d) * D_CONV;
    float acc = cb[k * D_INNER + d];
    #pragma unroll
    for (int j = 0; j < 4; j++) {
        int tau = t - 3 + j;
        if (tau >= 0) acc += w[j] * base[(long)tau * (2 * D_INNER)];
    }
    XSM[idx] = siluf(acc);
}

// ---------------- dt projection + softplus -> (dt, dt*x) pairs -------------
__global__ void dt_kernel(const float* __restrict__ DBL,
                          const float* __restrict__ XSM,
                          const float* __restrict__ wdt,
                          const float* __restrict__ bdt,
                          float* __restrict__ DD) {
    long idx = (long)blockIdx.x * blockDim.x + threadIdx.x;
    int d = (int)(idx % D_INNER);
    long rt = idx / D_INNER;
    int gp = (int)(rt >> 10);
    int k = gp >> 2;
    const float* row = DBL + rt * DBL_W;
    const float* w = wdt + ((long)k * D_INNER + d) * DT_RANK;
    float s = bdt[k * D_INNER + d];
    #pragma unroll
    for (int r = 0; r < DT_RANK; r++) s += row[r] * w[r];
    float dtv = (s > 20.0f) ? s : log1pf(expf(s));
    float xv = XSM[idx];
    *(float2*)(DD + idx * 2) = make_float2(dtv, dtv * xv);
}

// ---------------- chunked selective scan (16 lanes/channel, 4 chunks) -------
// Each chunk scans from h=0; partial y written to Y; running S = sum(dt)
// stored (chunks>0) for the analytic correction exp(A*S)*h_init.
__global__ void scan_kernel(const float* __restrict__ DD,
                            const float* __restrict__ DBL,
                            const float* __restrict__ Alog,
                            float* __restrict__ Y,
                            float* __restrict__ SC,
                            float* __restrict__ HST) {
    int gp = blockIdx.z;
    int c = blockIdx.y;
    int k = gp >> 2;
    int lane = threadIdx.x & 15;
    int d = (blockIdx.x << 4) + (threadIdx.x >> 4);
    float A = -expf(Alog[((long)k * D_INNER + d) * D_STATE + lane]);
    long t0 = (long)c * CL;
    const float2* ddp = (const float2*)(DD + ((long)gp * NN + t0) * 2 * D_INNER) + d;
    const float* bcp = DBL + ((long)gp * NN + t0) * DBL_W + DT_RANK + 4 * (lane & 7) + 2 * (lane >> 3);
    float* yp = Y + ((long)gp * NN + t0) * D_INNER + d;
    float* scp = SC + ((long)gp * NN + t0) * D_INNER + d;
    float h = 0.f, S = 0.f;
    for (int t = 0; t < CL; t++) {
        float2 dd = ddp[(long)t * D_INNER];
        float2 bc = *(const float2*)(bcp + (long)t * DBL_W);
        float dA = __expf(dd.x * A);
        h = dA * h + dd.y * bc.x;
        float p = h * bc.y;
        p += __shfl_xor_sync(0xffffffffu, p, 1);
        p += __shfl_xor_sync(0xffffffffu, p, 2);
        p += __shfl_xor_sync(0xffffffffu, p, 4);
        p += __shfl_xor_sync(0xffffffffu, p, 8);
        S += dd.x;
        if (lane == 0) {
            yp[(long)t * D_INNER] = p;
            if (c > 0) scp[(long)t * D_INNER] = S;
        }
    }
    if (c < NCH - 1)
        HST[(((long)gp * 3 + c) * D_INNER + d) * D_STATE + lane] = h;
}

// ---------------- chunk-boundary state chaining ----------------
__global__ void boundary_kernel(const float* __restrict__ HST,
                                const float* __restrict__ SC,
                                const float* __restrict__ Alog,
                                float* __restrict__ HINIT) {
    int idx = blockIdx.x * 256 + threadIdx.x;
    if (idx >= NPAIR * D_INNER * D_STATE) return;
    int gp = idx / (D_INNER * D_STATE);
    int r = idx % (D_INNER * D_STATE);
    int d = r >> 4, lane = r & 15;
    int k = gp >> 2;
    float A = -expf(Alog[((long)k * D_INNER + d) * D_STATE + lane]);
    float h = HST[(((long)gp * 3 + 0) * D_INNER + d) * D_STATE + lane];
    HINIT[(((long)gp * 3 + 0) * D_INNER + d) * D_STATE + lane] = h;   // init for chunk 1
    #pragma unroll
    for (int c = 1; c <= 2; c++) {
        float Send = SC[((long)gp * NN + (long)c * CL + CL - 1) * D_INNER + d];
        h = HST[(((long)gp * 3 + c) * D_INNER + d) * D_STATE + lane] + __expf(A * Send) * h;
        HINIT[(((long)gp * 3 + c) * D_INNER + d) * D_STATE + lane] = h;  // init for chunk c+1
    }
}

// ---------------- parallel correction: Y += C * (exp(A*S) .* h_init) --------
__global__ void corr_kernel(const float* __restrict__ SC,
                            const float* __restrict__ DBL,
                            const float* __restrict__ Alog,
                            const float* __restrict__ HINIT,
                            float* __restrict__ Y) {
    int gp = blockIdx.z;
    int c = blockIdx.y + 1;                        // chunks 1..3
    int k = gp >> 2;
    int lane = threadIdx.x & 15;
    int dtile = blockIdx.x % (D_INNER / 16);
    int ttile = blockIdx.x / (D_INNER / 16);
    int d = dtile * 16 + (threadIdx.x >> 4);
    long t0 = (long)c * CL + ttile * 32;
    float A = -expf(Alog[((long)k * D_INNER + d) * D_STATE + lane]);
    float hinit = HINIT[(((long)gp * 3 + (c - 1)) * D_INNER + d) * D_STATE + lane];
    const float* scp = SC + ((long)gp * NN + t0) * D_INNER + d;
    const float* bcp = DBL + ((long)gp * NN + t0) * DBL_W + DT_RANK + 4 * (lane & 7) + 2 * (lane >> 3);
    float* yp = Y + ((long)gp * NN + t0) * D_INNER + d;
    for (int t = 0; t < 32; t++) {
        float S = scp[(long)t * D_INNER];
        float2 bc = *(const float2*)(bcp + (long)t * DBL_W);
        float p = bc.y * __expf(A * S) * hinit;
        p += __shfl_xor_sync(0xffffffffu, p, 1);
        p += __shfl_xor_sync(0xffffffffu, p, 2);
        p += __shfl_xor_sync(0xffffffffu, p, 4);
        p += __shfl_xor_sync(0xffffffffu, p, 8);
        if (lane == 0) yp[(long)t * D_INNER] += p;
    }
}

// ---------------- combine ----------------
__global__ void combine_kernel(const float* __restrict__ Y,
                               const float* __restrict__ XSM,
                               const float* __restrict__ XZ,
                               const float* __restrict__ Dp,
                               bf16* __restrict__ YGh, bf16* __restrict__ YGl) {
    long i2 = (long)blockIdx.x * blockDim.x + threadIdx.x;
    long idx = i2 * 2;
    int d = (int)(idx % D_INNER);
    long rt = idx / D_INNER;
    int gp = (int)(rt >> 10);
    int k = gp >> 2;
    float2 z2 = *(const float2*)(XZ + rt * (2 * D_INNER) + D_INNER + d);
    float2 y2 = *(const float2*)(Y + idx);
    float2 x2 = *(const float2*)(XSM + idx);
    float2 D2 = *(const float2*)(Dp + (long)k * D_INNER + d);
    float v0 = (y2.x + x2.x * D2.x) * siluf(z2.x);
    float v1 = (y2.y + x2.y * D2.y) * siluf(z2.y);
    __nv_bfloat162 hv, lv;
    split_hl(v0, hv.x, lv.x);
    split_hl(v1, hv.y, lv.y);
    *(__nv_bfloat162*)(YGh + idx) = hv;
    *(__nv_bfloat162*)(YGl + idx) = lv;
}

// ---------------- LN out + residual + transpose ----------------
__global__ void ln_out_kernel(const float* __restrict__ H3,
                              const float* __restrict__ g,
                              const float* __restrict__ b,
                              const float* __restrict__ XS,
                              float* __restrict__ out) {
    int row = blockIdx.x;
    int bb = row >> 10, n = row & 1023;
    int c = threadIdx.x;
    float v = H3[(long)row * D_MODEL + c];
    float s = v, s2 = v * v;
    block_reduce2_192(s, s2);
    float mean = s * (1.0f / D_MODEL);
    float var = s2 * (1.0f / D_MODEL) - mean * mean;
    float rstd = rsqrtf(var + 1e-5f);
    float r = (v - mean) * rstd * g[c] + b[c] + XS[(long)row * D_MODEL + c];
    out[((long)bb * D_MODEL + c) * NN + n] = r;
}

// ---------------- host ----------------
extern "C" void kernel_launch(void* const* d_in, const int* in_sizes, int n_in,
                              void* d_out, int out_size) {
    const float* x      = (const float*)d_in[0];
    const float* norm_g = (const float*)d_in[1];
    const float* norm_b = (const float*)d_in[2];
    const float* in_w   = (const float*)d_in[3];
    const float* in_b   = (const float*)d_in[4];
    const float* m_in_w = (const float*)d_in[5];
    const float* m_cw   = (const float*)d_in[6];
    const float* m_cb   = (const float*)d_in[7];
    const float* m_xp_w = (const float*)d_in[8];
    const float* m_dt_w = (const float*)d_in[9];
    const float* m_dt_b = (const float*)d_in[10];
    const float* m_Alog = (const float*)d_in[11];
    const float* m_D    = (const float*)d_in[12];
    const float* m_out_w= (const float*)d_in[13];
    const float* f_w1   = (const float*)d_in[14];
    const float* f_b1   = (const float*)d_in[15];
    const float* f_w2   = (const float*)d_in[16];
    const float* f_b2   = (const float*)d_in[17];
    const float* o_w    = (const float*)d_in[18];
    const float* o_b    = (const float*)d_in[19];
    const float* on_g   = (const float*)d_in[20];
    const float* on_b   = (const float*)d_in[21];
    float* out = (float*)d_out;

    float *XS, *XZ, *XSM, *DBL, *DD, *SC, *HST, *HINIT, *Y, *H3;
    cudaGetSymbolAddress((void**)&XS,   g_XS);
    cudaGetSymbolAddress((void**)&XZ,   g_XZ);
    cudaGetSymbolAddress((void**)&XSM,  g_XSM);
    cudaGetSymbolAddress((void**)&DBL,  g_DBL);
    cudaGetSymbolAddress((void**)&DD,   g_DD);
    cudaGetSymbolAddress((void**)&SC,   g_SC);
    cudaGetSymbolAddress((void**)&HST,  g_HST);
    cudaGetSymbolAddress((void**)&HINIT,g_HINIT);
    cudaGetSymbolAddress((void**)&Y,    g_Y);
    cudaGetSymbolAddress((void**)&H3,   g_H3);

    bf16 *winh,*winl,*wminh,*wminl,*wmoh,*wmol,*wf1h,*wf1l,*wf2h,*wf2l,*woh,*wol;
    bf16 *XSh,*XSl,*XPh,*XPl,*YGh,*YGl,*FUSh,*FUSl,*H1h,*H1l,*H2h,*H2l;
    cudaGetSymbolAddress((void**)&winh, g_win_h);  cudaGetSymbolAddress((void**)&winl, g_win_l);
    cudaGetSymbolAddress((void**)&wminh,g_wmin_h); cudaGetSymbolAddress((void**)&wminl,g_wmin_l);
    cudaGetSymbolAddress((void**)&wmoh, g_wmo_h);  cudaGetSymbolAddress((void**)&wmol, g_wmo_l);
    cudaGetSymbolAddress((void**)&wf1h, g_wf1_h);  cudaGetSymbolAddress((void**)&wf1l, g_wf1_l);
    cudaGetSymbolAddress((void**)&wf2h, g_wf2_h);  cudaGetSymbolAddress((void**)&wf2l, g_wf2_l);
    cudaGetSymbolAddress((void**)&woh,  g_wo_h);   cudaGetSymbolAddress((void**)&wol,  g_wo_l);
    cudaGetSymbolAddress((void**)&XSh,  g_XSh);    cudaGetSymbolAddress((void**)&XSl,  g_XSl);
    cudaGetSymbolAddress((void**)&XPh,  g_XPh);    cudaGetSymbolAddress((void**)&XPl,  g_XPl);
    cudaGetSymbolAddress((void**)&YGh,  g_YGh);    cudaGetSymbolAddress((void**)&YGl,  g_YGl);
    cudaGetSymbolAddress((void**)&FUSh, g_FUSh);   cudaGetSymbolAddress((void**)&FUSl, g_FUSl);
    cudaGetSymbolAddress((void**)&H1h,  g_H1h);    cudaGetSymbolAddress((void**)&H1l,  g_H1l);
    cudaGetSymbolAddress((void**)&H2h,  g_H2h);    cudaGetSymbolAddress((void**)&H2l,  g_H2l);

    cudaFuncSetAttribute(gemm_mma<0,0>, cudaFuncAttributeMaxDynamicSharedMemorySize, GEMM_SMEM);
    cudaFuncSetAttribute(gemm_mma<1,0>, cudaFuncAttributeMaxDynamicSharedMemorySize, GEMM_SMEM);
    cudaFuncSetAttribute(gemm_mma<0,1>, cudaFuncAttributeMaxDynamicSharedMemorySize, GEMM_SMEM);

    Segs segs;
    segs.a[0] = { in_w,    winh,  winl,  D_MODEL*D_MODEL };
    segs.a[1] = { m_in_w,  wminh, wminl, 4*2*D_INNER*D_MODEL };
    segs.a[2] = { m_out_w, wmoh,  wmol,  4*D_MODEL*D_INNER };
    segs.a[3] = { f_w1,    wf1h,  wf1l,  2*D_MODEL*4*D_MODEL };
    segs.a[4] = { f_w2,    wf2h,  wf2l,  D_MODEL*2*D_MODEL };
    segs.a[5] = { o_w,     woh,   wol,   D_MODEL*D_MODEL };
    wconv<<<dim3(2304, 6, 1), 256>>>(segs);

    ln_in_kernel<<<ROWS, D_MODEL>>>(x, norm_g, norm_b, XS, XSh, XSl);

    gemm_mma<0,0><<<dim3(3, 32, 1), 256, GEMM_SMEM>>>(XSh, XSl, winh, winl, in_b,
        nullptr, XPh, XPl, ROWS, D_MODEL, D_MODEL, 0, 0, 0, 1, 0);

    gemm_mma<1,0><<<dim3(12, 8, 16), 256, GEMM_SMEM>>>(XPh, XPl, wminh, wminl, nullptr,
        XZ, nullptr, nullptr, NN, 2*D_INNER, D_MODEL,
        0, (long)2*D_INNER*D_MODEL, (long)NN*2*D_INNER, 4, 0);

    conv_silu_kernel<<<(NPAIR*NN*D_INNER)/256, 256>>>(XZ, m_cw, m_cb, XSM);

    gemm_abt<<<dim3(1, 16, 16), 256>>>(XSM, m_xp_w, DBL, NN, DBL_W, D_INNER,
        (long)NN*D_INNER, (long)DBL_W*D_INNER, (long)NN*DBL_W, 4);

    dt_kernel<<<(NPAIR*NN*D_INNER)/256, 256>>>(DBL, XSM, m_dt_w, m_dt_b, DD);

    scan_kernel<<<dim3(D_INNER/16, NCH, NPAIR), 256>>>(DD, DBL, m_Alog, Y, SC, HST);
    boundary_kernel<<<(NPAIR*D_INNER*D_STATE + 255)/256, 256>>>(HST, SC, m_Alog, HINIT);
    corr_kernel<<<dim3((D_INNER/16) * (CL/32), 3, NPAIR), 256>>>(SC, DBL, m_Alog, HINIT, Y);

    combine_kernel<<<(NPAIR*NN*D_INNER/2)/256, 256>>>(Y, XSM, XZ, m_D, YGh, YGl);

    gemm_mma<0,1><<<dim3(3, 8, 16), 256, GEMM_SMEM>>>(YGh, YGl, wmoh, wmol, nullptr,
        nullptr, FUSh, FUSl, NN, D_MODEL, D_INNER,
        (long)NN*D_INNER, (long)D_MODEL*D_INNER, 0, 4, 0);

    gemm_mma<0,0><<<dim3(6, 32, 1), 256, GEMM_SMEM>>>(FUSh, FUSl, wf1h, wf1l, f_b1,
        nullptr, H1h, H1l, ROWS, 2*D_MODEL, 4*D_MODEL, 0, 0, 0, 1, 1);

    gemm_mma<0,0><<<dim3(3, 32, 1), 256, GEMM_SMEM>>>(H1h, H1l, wf2h, wf2l, f_b2,
        nullptr, H2h, H2l, ROWS, D_MODEL, 2*D_MODEL, 0, 0, 0, 1, 0);

    gemm_mma<0,0><<<dim3(3, 32, 1), 256, GEMM_SMEM>>>(H2h, H2l, woh, wol, o_b,
        H3, nullptr, nullptr, ROWS, D_MODEL, D_MODEL, 0, 0, 0, 1, 0);

    ln_out_kernel<<<ROWS, D_MODEL>>>(H3, on_g, on_b, XS, out);
}

// round 13
// speedup vs baseline: 1.3119x; 1.3119x over previous
#include <cuda_runtime.h>
#include <cuda_bf16.h>
#include <math.h>

typedef __nv_bfloat16 bf16;

#define D_MODEL 192
#define D_STATE 16
#define D_CONV  4
#define D_INNER 384
#define DT_RANK 12
#define BB      4
#define NN      1024
#define NPAIR   16
#define ROWS    (BB*NN)
#define DBL_W   (DT_RANK + 2*D_STATE)

// ---------------- scratch ----------------
__device__ float g_XS [ROWS * D_MODEL];
__device__ float g_XZ [NPAIR * NN * 2 * D_INNER];
__device__ float g_XSM[NPAIR * NN * D_INNER];
__device__ float g_DBL[NPAIR * NN * DBL_W];
__device__ float g_DT [NPAIR * NN * D_INNER];
__device__ float g_Y  [NPAIR * NN * D_INNER];
__device__ float g_H3 [ROWS * D_MODEL];

__device__ bf16 g_win_h [D_MODEL*D_MODEL],     g_win_l [D_MODEL*D_MODEL];
__device__ bf16 g_wmin_h[4*2*D_INNER*D_MODEL], g_wmin_l[4*2*D_INNER*D_MODEL];
__device__ bf16 g_wmo_h [4*D_MODEL*D_INNER],   g_wmo_l [4*D_MODEL*D_INNER];
__device__ bf16 g_wf1_h [2*D_MODEL*4*D_MODEL], g_wf1_l [2*D_MODEL*4*D_MODEL];
__device__ bf16 g_wf2_h [D_MODEL*2*D_MODEL],   g_wf2_l [D_MODEL*2*D_MODEL];
__device__ bf16 g_wo_h  [D_MODEL*D_MODEL],     g_wo_l  [D_MODEL*D_MODEL];
__device__ bf16 g_XSh [ROWS*D_MODEL],     g_XSl [ROWS*D_MODEL];
__device__ bf16 g_XPh [ROWS*D_MODEL],     g_XPl [ROWS*D_MODEL];
__device__ bf16 g_YGh [NPAIR*NN*D_INNER], g_YGl [NPAIR*NN*D_INNER];
__device__ bf16 g_FUSh[ROWS*4*D_MODEL],   g_FUSl[ROWS*4*D_MODEL];
__device__ bf16 g_H1h [ROWS*2*D_MODEL],   g_H1l [ROWS*2*D_MODEL];
__device__ bf16 g_H2h [ROWS*D_MODEL],     g_H2l [ROWS*D_MODEL];

// ---------------- helpers ----------------
__device__ __forceinline__ float siluf(float x) { return x / (1.0f + expf(-x)); }

__device__ __forceinline__ int dirmap(int k, int t) {
    if (k == 0) return t;
    if (k == 1) return 1023 - t;
    if (k == 2) return ((t & 31) << 5) | (t >> 5);
    int tt = 1023 - t;
    return ((tt & 31) << 5) | (tt >> 5);
}

__device__ __forceinline__ void split_hl(float v, bf16& h, bf16& l) {
    h = __float2bfloat16(v);
    l = __float2bfloat16(v - __bfloat162float(h));
}

__device__ __forceinline__ void block_reduce2_192(float& a, float& b) {
    #pragma unroll
    for (int o = 16; o > 0; o >>= 1) {
        a += __shfl_xor_sync(0xffffffffu, a, o);
        b += __shfl_xor_sync(0xffffffffu, b, o);
    }
    __shared__ float sa[6], sb[6];
    int w = threadIdx.x >> 5, l = threadIdx.x & 31;
    if (l == 0) { sa[w] = a; sb[w] = b; }
    __syncthreads();
    if (threadIdx.x == 0) {
        float ta = 0.f, tb = 0.f;
        #pragma unroll
        for (int i = 0; i < 6; i++) { ta += sa[i]; tb += sb[i]; }
        sa[0] = ta; sb[0] = tb;
    }
    __syncthreads();
    a = sa[0]; b = sb[0];
}

__device__ __forceinline__ void ldsm4(unsigned& r0, unsigned& r1, unsigned& r2, unsigned& r3, unsigned addr) {
    asm volatile("ldmatrix.sync.aligned.m8n8.x4.shared.b16 {%0,%1,%2,%3}, [%4];"
                 : "=r"(r0), "=r"(r1), "=r"(r2), "=r"(r3) : "r"(addr));
}
__device__ __forceinline__ void mma16816(float* c, const unsigned* a, const unsigned* b) {
    asm volatile("mma.sync.aligned.m16n8k16.row.col.f32.bf16.bf16.f32 "
                 "{%0,%1,%2,%3}, {%4,%5,%6,%7}, {%8,%9}, {%0,%1,%2,%3};"
                 : "+f"(c[0]), "+f"(c[1]), "+f"(c[2]), "+f"(c[3])
                 : "r"(a[0]), "r"(a[1]), "r"(a[2]), "r"(a[3]), "r"(b[0]), "r"(b[1]));
}
__device__ __forceinline__ void cpasync16(unsigned dst, const void* src) {
    asm volatile("cp.async.cg.shared.global [%0], [%1], 16;\n" :: "r"(dst), "l"(src));
}
__device__ __forceinline__ void cp_commit() { asm volatile("cp.async.commit_group;\n" ::); }
__device__ __forceinline__ void cp_wait0()  { asm volatile("cp.async.wait_group 0;\n" ::); }

// ---------------- bf16 split tensor GEMM (2-stage, combined 3-product) ------
#define P_PITCH 40
#define AH_OFF  0
#define AL_OFF  10240
#define BH_OFF  20480
#define BL_OFF  25600
#define STG_B   30720
#define GEMM_SMEM (2*STG_B)

template<int DM, int SM>
__global__ __launch_bounds__(256, 3) void gemm_mma(
    const bf16* __restrict__ Ah, const bf16* __restrict__ Al,
    const bf16* __restrict__ Bh, const bf16* __restrict__ Bl,
    const float* __restrict__ bias,
    float* __restrict__ outF, bf16* __restrict__ oh, bf16* __restrict__ ol,
    int M, int N, int K, long sA, long sB, long sC, int bdiv, int act)
{
    extern __shared__ char dynsmem[];
    const unsigned smem0 = (unsigned)__cvta_generic_to_shared(dynsmem);

    const int t = threadIdx.x, lane = t & 31, w = t >> 5;
    const int wm = w & 3, wn = w >> 2;
    const int m0 = blockIdx.y * 128, n0 = blockIdx.x * 64;
    const int bz = blockIdx.z;
    const int kdir = bz >> 2;

    const bf16 *Abh, *Abl;
    if (DM == 1) { long o = (long)(bz & 3) * NN * K; Abh = Ah + o; Abl = Al + o; }
    else         { Abh = Ah + (long)bz * sA; Abl = Al + (long)bz * sA; }
    const bf16* Bbh = Bh + (long)(bz / bdiv) * sB;
    const bf16* Bbl = Bl + (long)(bz / bdiv) * sB;

    long aoff[2]; unsigned aswb[2];
    #pragma unroll
    for (int i = 0; i < 2; i++) {
        int u = t + i * 256, r = u >> 2, cu = u & 3;
        int rg = m0 + r;
        if (DM == 1) rg = dirmap(kdir, rg);
        aoff[i] = (long)rg * K + cu * 8;
        aswb[i] = (unsigned)((r * P_PITCH + cu * 8) * 2);
    }
    long boff; unsigned bswb;
    { int r = t >> 2, cu = t & 3;
      boff = (long)(n0 + r) * K + cu * 8;
      bswb = (unsigned)((r * P_PITCH + cu * 8) * 2); }

    const int KT = K >> 5;

    int arow[2], brow[2];
    #pragma unroll
    for (int mt = 0; mt < 2; mt++)
        arow[mt] = (wm * 32 + mt * 16 + (lane & 15)) * P_PITCH + ((lane >> 4) << 3);
    #pragma unroll
    for (int b2 = 0; b2 < 2; b2++)
        brow[b2] = (wn * 32 + b2 * 16 + (lane & 15)) * P_PITCH + ((lane >> 4) << 3);

    float acc[2][4][4] = {};

    auto issue = [&](int stg, int kt) {
        int k0 = kt << 5;
        unsigned sb = smem0 + (unsigned)(stg * STG_B);
        cpasync16(sb + AH_OFF + aswb[0], Abh + aoff[0] + k0);
        cpasync16(sb + AH_OFF + aswb[1], Abh + aoff[1] + k0);
        cpasync16(sb + AL_OFF + aswb[0], Abl + aoff[0] + k0);
        cpasync16(sb + AL_OFF + aswb[1], Abl + aoff[1] + k0);
        cpasync16(sb + BH_OFF + bswb,   Bbh + boff + k0);
        cpasync16(sb + BL_OFF + bswb,   Bbl + boff + k0);
    };

    issue(0, 0); cp_commit();

    for (int it = 0; it < KT; it++) {
        cp_wait0();
        __syncthreads();
        if (it + 1 < KT) { issue((it + 1) & 1, it + 1); cp_commit(); }
        unsigned base = smem0 + (unsigned)((it & 1) * STG_B);
        #pragma unroll
        for (int ks = 0; ks < 2; ks++) {
            unsigned ah[2][4], al[2][4], bh2[4][2], bl2[4][2];
            #pragma unroll
            for (int mt = 0; mt < 2; mt++)
                ldsm4(ah[mt][0], ah[mt][1], ah[mt][2], ah[mt][3],
                      base + AH_OFF + (unsigned)((arow[mt] + ks * 16) * 2));
            #pragma unroll
            for (int b2 = 0; b2 < 2; b2++) {
                unsigned r0, r1, r2, r3;
                ldsm4(r0, r1, r2, r3, base + BH_OFF + (unsigned)((brow[b2] + ks * 16) * 2));
                bh2[b2*2][0] = r0; bh2[b2*2+1][0] = r1;
                bh2[b2*2][1] = r2; bh2[b2*2+1][1] = r3;
            }
            #pragma unroll
            for (int mt = 0; mt < 2; mt++)
                #pragma unroll
                for (int nt = 0; nt < 4; nt++)
                    mma16816(acc[mt][nt], ah[mt], bh2[nt]);
            #pragma unroll
            for (int b2 = 0; b2 < 2; b2++) {
                unsigned r0, r1, r2, r3;
                ldsm4(r0, r1, r2, r3, base + BL_OFF + (unsigned)((brow[b2] + ks * 16) * 2));
                bl2[b2*2][0] = r0; bl2[b2*2+1][0] = r1;
                bl2[b2*2][1] = r2; bl2[b2*2+1][1] = r3;
            }
            #pragma unroll
            for (int mt = 0; mt < 2; mt++)
                #pragma unroll
                for (int nt = 0; nt < 4; nt++)
                    mma16816(acc[mt][nt], ah[mt], bl2[nt]);
            #pragma unroll
            for (int mt = 0; mt < 2; mt++)
                ldsm4(al[mt][0], al[mt][1], al[mt][2], al[mt][3],
                      base + AL_OFF + (unsigned)((arow[mt] + ks * 16) * 2));
            #pragma unroll
            for (int mt = 0; mt < 2; mt++)
                #pragma unroll
                for (int nt = 0; nt < 4; nt++)
                    mma16816(acc[mt][nt], al[mt], bh2[nt]);
        }
    }

    #pragma unroll
    for (int mt = 0; mt < 2; mt++)
    #pragma unroll
    for (int nt = 0; nt < 4; nt++) {
        int col = n0 + wn * 32 + nt * 8 + ((lane & 3) << 1);
        #pragma unroll
        for (int h = 0; h < 2; h++) {
            int rr = m0 + wm * 32 + mt * 16 + (lane >> 2) + h * 8;
            float v0 = acc[mt][nt][h*2+0], v1 = acc[mt][nt][h*2+1];
            if (bias) { v0 += bias[col]; v1 += bias[col+1]; }
            if (act) {
                v0 = 0.5f * v0 * (1.0f + erff(v0 * 0.70710678118654752f));
                v1 = 0.5f * v1 * (1.0f + erff(v1 * 0.70710678118654752f));
            }
            if (SM == 1) {
                int n = dirmap(kdir, rr);
                long o = ((long)((bz & 3) * NN + n)) * (4 * D_MODEL) + kdir * D_MODEL + col;
                __nv_bfloat162 hv, lv;
                split_hl(v0, hv.x, lv.x); split_hl(v1, hv.y, lv.y);
                *(__nv_bfloat162*)(oh + o) = hv;
                *(__nv_bfloat162*)(ol + o) = lv;
            } else if (outF) {
                *(float2*)(outF + (long)bz * sC + (long)rr * N + col) = make_float2(v0, v1);
            } else {
                long o = (long)rr * N + col;
                __nv_bfloat162 hv, lv;
                split_hl(v0, hv.x, lv.x); split_hl(v1, hv.y, lv.y);
                *(__nv_bfloat162*)(oh + o) = hv;
                *(__nv_bfloat162*)(ol + o) = lv;
            }
        }
    }
}

// ---------------- fp32 SIMT GEMM (x-proj, N=44 only) ----------------
__global__ __launch_bounds__(256) void gemm_abt(
    const float* __restrict__ A, const float* __restrict__ Bw,
    float* __restrict__ C, int M, int N, int K, long sA, long sB, long sC, int bdiv)
{
    int bz = blockIdx.z;
    const float* Ab = A + (long)bz * sA;
    const float* Bb = Bw + (long)(bz / bdiv) * sB;
    float* Cb = C + (long)bz * sC;
    __shared__ float As[16][64];
    __shared__ float Bs[16][64];
    int t = threadIdx.x;
    int tr = t >> 4, tc = t & 15;
    int m0 = blockIdx.y << 6, n0 = blockIdx.x << 6;
    int lm = t >> 2, lk = (t & 3) << 2;
    float acc[4][4] = {};
    int nK = K >> 4;
    for (int kb = 0; kb < nK; kb++) {
        int k0 = kb << 4;
        float4 av = make_float4(0.f,0.f,0.f,0.f), bv = make_float4(0.f,0.f,0.f,0.f);
        if (m0 + lm < M) av = *(const float4*)(Ab + (long)(m0 + lm) * K + k0 + lk);
        if (n0 + lm < N) bv = *(const float4*)(Bb + (long)(n0 + lm) * K + k0 + lk);
        __syncthreads();
        As[lk+0][lm]=av.x; As[lk+1][lm]=av.y; As[lk+2][lm]=av.z; As[lk+3][lm]=av.w;
        Bs[lk+0][lm]=bv.x; Bs[lk+1][lm]=bv.y; Bs[lk+2][lm]=bv.z; Bs[lk+3][lm]=bv.w;
        __syncthreads();
        #pragma unroll
        for (int kk = 0; kk < 16; kk++) {
            float4 a4 = *(const float4*)&As[kk][tr << 2];
            float4 b4 = *(const float4*)&Bs[kk][tc << 2];
            float ar[4] = {a4.x,a4.y,a4.z,a4.w}, br[4] = {b4.x,b4.y,b4.z,b4.w};
            #pragma unroll
            for (int i = 0; i < 4; i++)
                #pragma unroll
                for (int j = 0; j < 4; j++) acc[i][j] += ar[i] * br[j];
        }
    }
    #pragma unroll
    for (int i = 0; i < 4; i++) {
        int m = m0 + (tr << 2) + i;
        if (m >= M) continue;
        #pragma unroll
        for (int j = 0; j < 4; j++) {
            int n = n0 + (tc << 2) + j;
            if (n >= N) continue;
            Cb[(long)m * N + n] = acc[i][j];
        }
    }
}

// ---------------- weight fp32 -> hi/lo ----------------
struct Seg { const float* s; bf16* h; bf16* l; int n; };
struct Segs { Seg a[6]; };
__global__ void wconv(Segs P) {
    Seg sg = P.a[blockIdx.y];
    int i = blockIdx.x * 256 + threadIdx.x;
    if (i < sg.n) { bf16 h, l; split_hl(sg.s[i], h, l); sg.h[i] = h; sg.l[i] = l; }
}

// ---------------- LN in ----------------
__global__ void ln_in_kernel(const float* __restrict__ x,
                             const float* __restrict__ g,
                             const float* __restrict__ b,
                             float* __restrict__ XS,
                             bf16* __restrict__ XSh, bf16* __restrict__ XSl) {
    int row = blockIdx.x;
    int bb = row >> 10, n = row & 1023;
    int c = threadIdx.x;
    float v = x[((long)bb * D_MODEL + c) * NN + n];
    float s = v, s2 = v * v;
    block_reduce2_192(s, s2);
    float mean = s * (1.0f / D_MODEL);
    float var = s2 * (1.0f / D_MODEL) - mean * mean;
    float rstd = rsqrtf(var + 1e-5f);
    float r = (v - mean) * rstd * g[c] + b[c];
    long o = (long)row * D_MODEL + c;
    XS[o] = r;
    bf16 h, l; split_hl(r, h, l);
    XSh[o] = h; XSl[o] = l;
}

// ---------------- conv + silu (x4 vectorized over d) ----------------
__global__ void conv_silu_kernel(const float* __restrict__ XZ,
                                 const float* __restrict__ cw,
                                 const float* __restrict__ cb,
                                 float* __restrict__ XSM) {
    long i4 = (long)blockIdx.x * blockDim.x + threadIdx.x;   // NPAIR*NN*96
    int d4 = (int)(i4 % (D_INNER / 4)) * 4;
    long rt = i4 / (D_INNER / 4);          // gp*1024 + t
    int t = (int)(rt & 1023);
    int gp = (int)(rt >> 10);
    int k = gp >> 2;
    float4 acc = *(const float4*)(cb + (long)k * D_INNER + d4);
    float4 wv[4];
    #pragma unroll
    for (int c = 0; c < 4; c++)
        wv[c] = *(const float4*)(cw + ((long)k * D_INNER + d4 + c) * D_CONV);
    const float* base = XZ + ((long)gp * NN) * (2 * D_INNER) + d4;
    #pragma unroll
    for (int j = 0; j < 4; j++) {
        int tau = t - 3 + j;
        if (tau >= 0) {
            float4 xv = *(const float4*)(base + (long)tau * (2 * D_INNER));
            float wj0 = (&wv[0].x)[j], wj1 = (&wv[1].x)[j];
            float wj2 = (&wv[2].x)[j], wj3 = (&wv[3].x)[j];
            acc.x += wj0 * xv.x; acc.y += wj1 * xv.y;
            acc.z += wj2 * xv.z; acc.w += wj3 * xv.w;
        }
    }
    float4 o;
    o.x = siluf(acc.x); o.y = siluf(acc.y); o.z = siluf(acc.z); o.w = siluf(acc.w);
    *(float4*)(XSM + rt * D_INNER + d4) = o;
}

// ---------------- dt projection + softplus (x2 over d, row loaded once) ----
__global__ void dt_kernel(const float* __restrict__ DBL,
                          const float* __restrict__ wdt,
                          const float* __restrict__ bdt,
                          float* __restrict__ DT) {
    long i2 = (long)blockIdx.x * blockDim.x + threadIdx.x;   // NPAIR*NN*192
    int d2 = (int)(i2 % (D_INNER / 2)) * 2;
    long rt = i2 / (D_INNER / 2);
    int gp = (int)(rt >> 10);
    int k = gp >> 2;
    float4 r0 = *(const float4*)(DBL + rt * DBL_W);
    float4 r1 = *(const float4*)(DBL + rt * DBL_W + 4);
    float4 r2 = *(const float4*)(DBL + rt * DBL_W + 8);
    float2 bb = *(const float2*)(bdt + (long)k * D_INNER + d2);
    float s0 = bb.x, s1 = bb.y;
    const float* w0 = wdt + ((long)k * D_INNER + d2) * DT_RANK;
    const float* w1 = w0 + DT_RANK;
    #pragma unroll
    for (int i = 0; i < 3; i++) {
        float4 w0v = *(const float4*)(w0 + i * 4);
        float4 w1v = *(const float4*)(w1 + i * 4);
        const float4 rv = (i == 0) ? r0 : (i == 1) ? r1 : r2;
        s0 += rv.x * w0v.x + rv.y * w0v.y + rv.z * w0v.z + rv.w * w0v.w;
        s1 += rv.x * w1v.x + rv.y * w1v.y + rv.z * w1v.z + rv.w * w1v.w;
    }
    float d0 = (s0 > 20.0f) ? s0 : log1pf(expf(s0));
    float d1 = (s1 > 20.0f) ? s1 : log1pf(expf(s1));
    *(float2*)(DT + rt * D_INNER + d2) = make_float2(d0, d1);
}

// ---------------- selective scan (round-10 exact: writes fp32 Y) ----------
__global__ void scan_kernel(const float* __restrict__ DT,
                            const float* __restrict__ XSM,
                            const float* __restrict__ DBL,
                            const float* __restrict__ Alog,
                            float* __restrict__ Y) {
    int gp = blockIdx.z;
    int k = gp >> 2;
    int lane = threadIdx.x & 15;
    int d = (blockIdx.x << 3) + (threadIdx.x >> 4);
    float A = -expf(Alog[((long)k * D_INNER + d) * D_STATE + lane]);
    const float* dtp = DT  + ((long)gp * NN) * D_INNER + d;
    const float* xp_ = XSM + ((long)gp * NN) * D_INNER + d;
    const float* bp  = DBL + ((long)gp * NN) * DBL_W + DT_RANK + lane;
    const float* cp  = bp + D_STATE;
    float* yp = Y + ((long)gp * NN) * D_INNER + d;
    float h = 0.f;
    for (int t = 0; t < NN; t++) {
        float dt = dtp[(long)t * D_INNER];
        float xv = xp_[(long)t * D_INNER];
        float Bv = bp[(long)t * DBL_W];
        float Cv = cp[(long)t * DBL_W];
        float dA = __expf(dt * A);
        h = dA * h + (dt * xv) * Bv;
        float p = h * Cv;
        p += __shfl_xor_sync(0xffffffffu, p, 1);
        p += __shfl_xor_sync(0xffffffffu, p, 2);
        p += __shfl_xor_sync(0xffffffffu, p, 4);
        p += __shfl_xor_sync(0xffffffffu, p, 8);
        if (lane == 0) yp[(long)t * D_INNER] = p;
    }
}

// ---------------- combine (x4 vectorized) ----------------
__global__ void combine_kernel(const float* __restrict__ Y,
                               const float* __restrict__ XSM,
                               const float* __restrict__ XZ,
                               const float* __restrict__ Dp,
                               bf16* __restrict__ YGh, bf16* __restrict__ YGl) {
    long i4 = (long)blockIdx.x * blockDim.x + threadIdx.x;   // NPAIR*NN*96
    long idx = i4 * 4;
    int d = (int)(idx % D_INNER);
    long rt = idx / D_INNER;
    int gp = (int)(rt >> 10);
    int k = gp >> 2;
    float4 z4 = *(const float4*)(XZ + rt * (2 * D_INNER) + D_INNER + d);
    float4 y4 = *(const float4*)(Y + idx);
    float4 x4 = *(const float4*)(XSM + idx);
    float4 D4 = *(const float4*)(Dp + (long)k * D_INNER + d);
    float v0 = (y4.x + x4.x * D4.x) * siluf(z4.x);
    float v1 = (y4.y + x4.y * D4.y) * siluf(z4.y);
    float v2 = (y4.z + x4.z * D4.z) * siluf(z4.z);
    float v3 = (y4.w + x4.w * D4.w) * siluf(z4.w);
    __nv_bfloat162 h0, l0, h1, l1;
    split_hl(v0, h0.x, l0.x); split_hl(v1, h0.y, l0.y);
    split_hl(v2, h1.x, l1.x); split_hl(v3, h1.y, l1.y);
    *(__nv_bfloat162*)(YGh + idx)     = h0;
    *(__nv_bfloat162*)(YGh + idx + 2) = h1;
    *(__nv_bfloat162*)(YGl + idx)     = l0;
    *(__nv_bfloat162*)(YGl + idx + 2) = l1;
}

// ---------------- LN out + residual + transpose ----------------
__global__ void ln_out_kernel(const float* __restrict__ H3,
                              const float* __restrict__ g,
                              const float* __restrict__ b,
                              const float* __restrict__ XS,
                              float* __restrict__ out) {
    int row = blockIdx.x;
    int bb = row >> 10, n = row & 1023;
    int c = threadIdx.x;
    float v = H3[(long)row * D_MODEL + c];
    float s = v, s2 = v * v;
    block_reduce2_192(s, s2);
    float mean = s * (1.0f / D_MODEL);
    float var = s2 * (1.0f / D_MODEL) - mean * mean;
    float rstd = rsqrtf(var + 1e-5f);
    float r = (v - mean) * rstd * g[c] + b[c] + XS[(long)row * D_MODEL + c];
    out[((long)bb * D_MODEL + c) * NN + n] = r;
}

// ---------------- host ----------------
extern "C" void kernel_launch(void* const* d_in, const int* in_sizes, int n_in,
                              void* d_out, int out_size) {
    const float* x      = (const float*)d_in[0];
    const float* norm_g = (const float*)d_in[1];
    const float* norm_b = (const float*)d_in[2];
    const float* in_w   = (const float*)d_in[3];
    const float* in_b   = (const float*)d_in[4];
    const float* m_in_w = (const float*)d_in[5];
    const float* m_cw   = (const float*)d_in[6];
    const float* m_cb   = (const float*)d_in[7];
    const float* m_xp_w = (const float*)d_in[8];
    const float* m_dt_w = (const float*)d_in[9];
    const float* m_dt_b = (const float*)d_in[10];
    const float* m_Alog = (const float*)d_in[11];
    const float* m_D    = (const float*)d_in[12];
    const float* m_out_w= (const float*)d_in[13];
    const float* f_w1   = (const float*)d_in[14];
    const float* f_b1   = (const float*)d_in[15];
    const float* f_w2   = (const float*)d_in[16];
    const float* f_b2   = (const float*)d_in[17];
    const float* o_w    = (const float*)d_in[18];
    const float* o_b    = (const float*)d_in[19];
    const float* on_g   = (const float*)d_in[20];
    const float* on_b   = (const float*)d_in[21];
    float* out = (float*)d_out;

    float *XS, *XZ, *XSM, *DBL, *DT, *Y, *H3;
    cudaGetSymbolAddress((void**)&XS,  g_XS);
    cudaGetSymbolAddress((void**)&XZ,  g_XZ);
    cudaGetSymbolAddress((void**)&XSM, g_XSM);
    cudaGetSymbolAddress((void**)&DBL, g_DBL);
    cudaGetSymbolAddress((void**)&DT,  g_DT);
    cudaGetSymbolAddress((void**)&Y,   g_Y);
    cudaGetSymbolAddress((void**)&H3,  g_H3);

    bf16 *winh,*winl,*wminh,*wminl,*wmoh,*wmol,*wf1h,*wf1l,*wf2h,*wf2l,*woh,*wol;
    bf16 *XSh,*XSl,*XPh,*XPl,*YGh,*YGl,*FUSh,*FUSl,*H1h,*H1l,*H2h,*H2l;
    cudaGetSymbolAddress((void**)&winh, g_win_h);  cudaGetSymbolAddress((void**)&winl, g_win_l);
    cudaGetSymbolAddress((void**)&wminh,g_wmin_h); cudaGetSymbolAddress((void**)&wminl,g_wmin_l);
    cudaGetSymbolAddress((void**)&wmoh, g_wmo_h);  cudaGetSymbolAddress((void**)&wmol, g_wmo_l);
    cudaGetSymbolAddress((void**)&wf1h, g_wf1_h);  cudaGetSymbolAddress((void**)&wf1l, g_wf1_l);
    cudaGetSymbolAddress((void**)&wf2h, g_wf2_h);  cudaGetSymbolAddress((void**)&wf2l, g_wf2_l);
    cudaGetSymbolAddress((void**)&woh,  g_wo_h);   cudaGetSymbolAddress((void**)&wol,  g_wo_l);
    cudaGetSymbolAddress((void**)&XSh,  g_XSh);    cudaGetSymbolAddress((void**)&XSl,  g_XSl);
    cudaGetSymbolAddress((void**)&XPh,  g_XPh);    cudaGetSymbolAddress((void**)&XPl,  g_XPl);
    cudaGetSymbolAddress((void**)&YGh,  g_YGh);    cudaGetSymbolAddress((void**)&YGl,  g_YGl);
    cudaGetSymbolAddress((void**)&FUSh, g_FUSh);   cudaGetSymbolAddress((void**)&FUSl, g_FUSl);
    cudaGetSymbolAddress((void**)&H1h,  g_H1h);    cudaGetSymbolAddress((void**)&H1l,  g_H1l);
    cudaGetSymbolAddress((void**)&H2h,  g_H2h);    cudaGetSymbolAddress((void**)&H2l,  g_H2l);

    cudaFuncSetAttribute(gemm_mma<0,0>, cudaFuncAttributeMaxDynamicSharedMemorySize, GEMM_SMEM);
    cudaFuncSetAttribute(gemm_mma<1,0>, cudaFuncAttributeMaxDynamicSharedMemorySize, GEMM_SMEM);
    cudaFuncSetAttribute(gemm_mma<0,1>, cudaFuncAttributeMaxDynamicSharedMemorySize, GEMM_SMEM);

    Segs segs;
    segs.a[0] = { in_w,    winh,  winl,  D_MODEL*D_MODEL };
    segs.a[1] = { m_in_w,  wminh, wminl, 4*2*D_INNER*D_MODEL };
    segs.a[2] = { m_out_w, wmoh,  wmol,  4*D_MODEL*D_INNER };
    segs.a[3] = { f_w1,    wf1h,  wf1l,  2*D_MODEL*4*D_MODEL };
    segs.a[4] = { f_w2,    wf2h,  wf2l,  D_MODEL*2*D_MODEL };
    segs.a[5] = { o_w,     woh,   wol,   D_MODEL*D_MODEL };
    wconv<<<dim3(2304, 6, 1), 256>>>(segs);

    ln_in_kernel<<<ROWS, D_MODEL>>>(x, norm_g, norm_b, XS, XSh, XSl);

    gemm_mma<0,0><<<dim3(3, 32, 1), 256, GEMM_SMEM>>>(XSh, XSl, winh, winl, in_b,
        nullptr, XPh, XPl, ROWS, D_MODEL, D_MODEL, 0, 0, 0, 1, 0);

    gemm_mma<1,0><<<dim3(12, 8, 16), 256, GEMM_SMEM>>>(XPh, XPl, wminh, wminl, nullptr,
        XZ, nullptr, nullptr, NN, 2*D_INNER, D_MODEL,
        0, (long)2*D_INNER*D_MODEL, (long)NN*2*D_INNER, 4, 0);

    conv_silu_kernel<<<(NPAIR*NN*(D_INNER/4))/256, 256>>>(XZ, m_cw, m_cb, XSM);

    gemm_abt<<<dim3(1, 16, 16), 256>>>(XSM, m_xp_w, DBL, NN, DBL_W, D_INNER,
        (long)NN*D_INNER, (long)DBL_W*D_INNER, (long)NN*DBL_W, 4);

    dt_kernel<<<(NPAIR*NN*(D_INNER/2))/256, 256>>>(DBL, m_dt_w, m_dt_b, DT);

    scan_kernel<<<dim3(D_INNER/8, 1, NPAIR), 128>>>(DT, XSM, DBL, m_Alog, Y);

    combine_kernel<<<(NPAIR*NN*(D_INNER/4))/256, 256>>>(Y, XSM, XZ, m_D, YGh, YGl);

    gemm_mma<0,1><<<dim3(3, 8, 16), 256, GEMM_SMEM>>>(YGh, YGl, wmoh, wmol, nullptr,
        nullptr, FUSh, FUSl, NN, D_MODEL, D_INNER,
        (long)NN*D_INNER, (long)D_MODEL*D_INNER, 0, 4, 0);

    gemm_mma<0,0><<<dim3(6, 32, 1), 256, GEMM_SMEM>>>(FUSh, FUSl, wf1h, wf1l, f_b1,
        nullptr, H1h, H1l, ROWS, 2*D_MODEL, 4*D_MODEL, 0, 0, 0, 1, 1);

    gemm_mma<0,0><<<dim3(3, 32, 1), 256, GEMM_SMEM>>>(H1h, H1l, wf2h, wf2l, f_b2,
        nullptr, H2h, H2l, ROWS, D_MODEL, 2*D_MODEL, 0, 0, 0, 1, 0);

    gemm_mma<0,0><<<dim3(3, 32, 1), 256, GEMM_SMEM>>>(H2h, H2l, woh, wol, o_b,
        H3, nullptr, nullptr, ROWS, D_MODEL, D_MODEL, 0, 0, 0, 1, 0);

    ln_out_kernel<<<ROWS, D_MODEL>>>(H3, on_g, on_b, XS, out);
}

// round 15
// speedup vs baseline: 1.3401x; 1.0215x over previous
#include <cuda_runtime.h>
#include <cuda_bf16.h>
#include <math.h>

typedef __nv_bfloat16 bf16;

#define D_MODEL 192
#define D_STATE 16
#define D_CONV  4
#define D_INNER 384
#define DT_RANK 12
#define BB      4
#define NN      1024
#define NPAIR   16
#define ROWS    (BB*NN)
#define DBL_W   (DT_RANK + 2*D_STATE)

// ---------------- scratch ----------------
__device__ float g_XS [ROWS * D_MODEL];
__device__ float g_XZ [NPAIR * NN * 2 * D_INNER];
__device__ float g_XSM[NPAIR * NN * D_INNER];
__device__ float g_DBL[NPAIR * NN * DBL_W];
__device__ float g_DT [NPAIR * NN * D_INNER];
__device__ float g_Y  [NPAIR * NN * D_INNER];
__device__ float g_H3 [ROWS * D_MODEL];

__device__ bf16 g_win_h [D_MODEL*D_MODEL],     g_win_l [D_MODEL*D_MODEL];
__device__ bf16 g_wmin_h[4*2*D_INNER*D_MODEL], g_wmin_l[4*2*D_INNER*D_MODEL];
__device__ bf16 g_wmo_h [4*D_MODEL*D_INNER],   g_wmo_l [4*D_MODEL*D_INNER];
__device__ bf16 g_wf1_h [2*D_MODEL*4*D_MODEL], g_wf1_l [2*D_MODEL*4*D_MODEL];
__device__ bf16 g_wf2_h [D_MODEL*2*D_MODEL],   g_wf2_l [D_MODEL*2*D_MODEL];
__device__ bf16 g_wo_h  [D_MODEL*D_MODEL],     g_wo_l  [D_MODEL*D_MODEL];
__device__ bf16 g_XSh [ROWS*D_MODEL],     g_XSl [ROWS*D_MODEL];
__device__ bf16 g_XPh [ROWS*D_MODEL],     g_XPl [ROWS*D_MODEL];
__device__ bf16 g_YGh [NPAIR*NN*D_INNER], g_YGl [NPAIR*NN*D_INNER];
__device__ bf16 g_FUSh[ROWS*4*D_MODEL],   g_FUSl[ROWS*4*D_MODEL];
__device__ bf16 g_H1h [ROWS*2*D_MODEL],   g_H1l [ROWS*2*D_MODEL];
__device__ bf16 g_H2h [ROWS*D_MODEL],     g_H2l [ROWS*D_MODEL];

// ---------------- helpers ----------------
__device__ __forceinline__ float siluf(float x) { return x / (1.0f + expf(-x)); }

__device__ __forceinline__ int dirmap(int k, int t) {
    if (k == 0) return t;
    if (k == 1) return 1023 - t;
    if (k == 2) return ((t & 31) << 5) | (t >> 5);
    int tt = 1023 - t;
    return ((tt & 31) << 5) | (tt >> 5);
}

__device__ __forceinline__ void split_hl(float v, bf16& h, bf16& l) {
    h = __float2bfloat16(v);
    l = __float2bfloat16(v - __bfloat162float(h));
}

__device__ __forceinline__ void block_reduce2_192(float& a, float& b) {
    #pragma unroll
    for (int o = 16; o > 0; o >>= 1) {
        a += __shfl_xor_sync(0xffffffffu, a, o);
        b += __shfl_xor_sync(0xffffffffu, b, o);
    }
    __shared__ float sa[6], sb[6];
    int w = threadIdx.x >> 5, l = threadIdx.x & 31;
    if (l == 0) { sa[w] = a; sb[w] = b; }
    __syncthreads();
    if (threadIdx.x == 0) {
        float ta = 0.f, tb = 0.f;
        #pragma unroll
        for (int i = 0; i < 6; i++) { ta += sa[i]; tb += sb[i]; }
        sa[0] = ta; sb[0] = tb;
    }
    __syncthreads();
    a = sa[0]; b = sb[0];
}

__device__ __forceinline__ void ldsm4(unsigned& r0, unsigned& r1, unsigned& r2, unsigned& r3, unsigned addr) {
    asm volatile("ldmatrix.sync.aligned.m8n8.x4.shared.b16 {%0,%1,%2,%3}, [%4];"
                 : "=r"(r0), "=r"(r1), "=r"(r2), "=r"(r3) : "r"(addr));
}
__device__ __forceinline__ void mma16816(float* c, const unsigned* a, const unsigned* b) {
    asm volatile("mma.sync.aligned.m16n8k16.row.col.f32.bf16.bf16.f32 "
                 "{%0,%1,%2,%3}, {%4,%5,%6,%7}, {%8,%9}, {%0,%1,%2,%3};"
                 : "+f"(c[0]), "+f"(c[1]), "+f"(c[2]), "+f"(c[3])
                 : "r"(a[0]), "r"(a[1]), "r"(a[2]), "r"(a[3]), "r"(b[0]), "r"(b[1]));
}
__device__ __forceinline__ void cpasync16(unsigned dst, const void* src) {
    asm volatile("cp.async.cg.shared.global [%0], [%1], 16;\n" :: "r"(dst), "l"(src));
}
__device__ __forceinline__ void cp_commit() { asm volatile("cp.async.commit_group;\n" ::); }
__device__ __forceinline__ void cp_wait0()  { asm volatile("cp.async.wait_group 0;\n" ::); }

// ---------------- bf16 split tensor GEMM (2-stage, combined 3-product) ------
// TM = M-tile (128 or 64). BM=128: 4 m-warp-groups x 2 n-groups (32 cols),
// 3 CTAs/SM. BM=64: 2 m-groups x 4 n-groups (16 cols), 4 CTAs/SM.
#define P_PITCH 40

template<int TM> struct GCfg {
    static const int NWM = TM / 32;           // m warp groups (4 or 2)
    static const int NT  = NWM;               // n-tiles (n8) per warp (4 or 2)
    static const int NB2 = NT / 2 ? NT / 2 : 1; // ldsm.x4 count for B (2 or 1)
    static const int AU  = TM / 64;           // A staging units per thread (2 or 1)
    static const int AHOFF = 0;
    static const int ALOFF = TM * P_PITCH * 2;
    static const int BHOFF = 2 * TM * P_PITCH * 2;
    static const int BLOFF = BHOFF + 64 * P_PITCH * 2;
    static const int STG   = BLOFF + 64 * P_PITCH * 2;
    static const int SMEM  = 2 * STG;
    static const int OCC   = (TM == 64) ? 4 : 3;
};

template<int DM, int SM, int TM>
__global__ __launch_bounds__(256, GCfg<TM>::OCC) void gemm_mma(
    const bf16* __restrict__ Ah, const bf16* __restrict__ Al,
    const bf16* __restrict__ Bh, const bf16* __restrict__ Bl,
    const float* __restrict__ bias,
    float* __restrict__ outF, bf16* __restrict__ oh, bf16* __restrict__ ol,
    int M, int N, int K, long sA, long sB, long sC, int bdiv, int act)
{
    typedef GCfg<TM> C;
    extern __shared__ char dynsmem[];
    const unsigned smem0 = (unsigned)__cvta_generic_to_shared(dynsmem);

    const int t = threadIdx.x, lane = t & 31, w = t >> 5;
    const int wm = w & (C::NWM - 1), wn = w / C::NWM;
    const int m0 = blockIdx.y * TM, n0 = blockIdx.x * 64;
    const int bz = blockIdx.z;
    const int kdir = bz >> 2;

    const bf16 *Abh, *Abl;
    if (DM == 1) { long o = (long)(bz & 3) * NN * K; Abh = Ah + o; Abl = Al + o; }
    else         { Abh = Ah + (long)bz * sA; Abl = Al + (long)bz * sA; }
    const bf16* Bbh = Bh + (long)(bz / bdiv) * sB;
    const bf16* Bbl = Bl + (long)(bz / bdiv) * sB;

    long aoff[C::AU]; unsigned aswb[C::AU];
    #pragma unroll
    for (int i = 0; i < C::AU; i++) {
        int u = t + i * 256, r = u >> 2, cu = u & 3;
        int rg = m0 + r;
        if (DM == 1) rg = dirmap(kdir, rg);
        aoff[i] = (long)rg * K + cu * 8;
        aswb[i] = (unsigned)((r * P_PITCH + cu * 8) * 2);
    }
    long boff; unsigned bswb;
    { int r = t >> 2, cu = t & 3;
      boff = (long)(n0 + r) * K + cu * 8;
      bswb = (unsigned)((r * P_PITCH + cu * 8) * 2); }

    const int KT = K >> 5;

    int arow[2], brow[C::NB2];
    #pragma unroll
    for (int mt = 0; mt < 2; mt++)
        arow[mt] = (wm * 32 + mt * 16 + (lane & 15)) * P_PITCH + ((lane >> 4) << 3);
    #pragma unroll
    for (int b2 = 0; b2 < C::NB2; b2++)
        brow[b2] = (wn * (8 * C::NT) + b2 * 16 + (lane & 15)) * P_PITCH + ((lane >> 4) << 3);

    float acc[2][C::NT][4];
    #pragma unroll
    for (int i = 0; i < 2; i++)
        #pragma unroll
        for (int j = 0; j < C::NT; j++)
            #pragma unroll
            for (int q = 0; q < 4; q++) acc[i][j][q] = 0.f;

    auto issue = [&](int stg, int kt) {
        int k0 = kt << 5;
        unsigned sb = smem0 + (unsigned)(stg * C::STG);
        #pragma unroll
        for (int i = 0; i < C::AU; i++) {
            cpasync16(sb + C::AHOFF + aswb[i], Abh + aoff[i] + k0);
            cpasync16(sb + C::ALOFF + aswb[i], Abl + aoff[i] + k0);
        }
        cpasync16(sb + C::BHOFF + bswb, Bbh + boff + k0);
        cpasync16(sb + C::BLOFF + bswb, Bbl + boff + k0);
    };

    issue(0, 0); cp_commit();

    for (int it = 0; it < KT; it++) {
        cp_wait0();
        __syncthreads();
        if (it + 1 < KT) { issue((it + 1) & 1, it + 1); cp_commit(); }
        unsigned base = smem0 + (unsigned)((it & 1) * C::STG);
        #pragma unroll
        for (int ks = 0; ks < 2; ks++) {
            unsigned ah[2][4], al[2][4], bh2[C::NT][2], bl2[C::NT][2];
            #pragma unroll
            for (int mt = 0; mt < 2; mt++)
                ldsm4(ah[mt][0], ah[mt][1], ah[mt][2], ah[mt][3],
                      base + C::AHOFF + (unsigned)((arow[mt] + ks * 16) * 2));
            #pragma unroll
            for (int b2 = 0; b2 < C::NB2; b2++) {
                unsigned r0, r1, r2, r3;
                ldsm4(r0, r1, r2, r3, base + C::BHOFF + (unsigned)((brow[b2] + ks * 16) * 2));
                bh2[b2*2][0] = r0; bh2[b2*2+1][0] = r1;
                bh2[b2*2][1] = r2; bh2[b2*2+1][1] = r3;
            }
            #pragma unroll
            for (int mt = 0; mt < 2; mt++)
                #pragma unroll
                for (int nt = 0; nt < C::NT; nt++)
                    mma16816(acc[mt][nt], ah[mt], bh2[nt]);
            #pragma unroll
            for (int b2 = 0; b2 < C::NB2; b2++) {
                unsigned r0, r1, r2, r3;
                ldsm4(r0, r1, r2, r3, base + C::BLOFF + (unsigned)((brow[b2] + ks * 16) * 2));
                bl2[b2*2][0] = r0; bl2[b2*2+1][0] = r1;
                bl2[b2*2][1] = r2; bl2[b2*2+1][1] = r3;
            }
            #pragma unroll
            for (int mt = 0; mt < 2; mt++)
                #pragma unroll
                for (int nt = 0; nt < C::NT; nt++)
                    mma16816(acc[mt][nt], ah[mt], bl2[nt]);
            #pragma unroll
            for (int mt = 0; mt < 2; mt++)
                ldsm4(al[mt][0], al[mt][1], al[mt][2], al[mt][3],
                      base + C::ALOFF + (unsigned)((arow[mt] + ks * 16) * 2));
            #pragma unroll
            for (int mt = 0; mt < 2; mt++)
                #pragma unroll
                for (int nt = 0; nt < C::NT; nt++)
                    mma16816(acc[mt][nt], al[mt], bh2[nt]);
        }
    }

    #pragma unroll
    for (int mt = 0; mt < 2; mt++)
    #pragma unroll
    for (int nt = 0; nt < C::NT; nt++) {
        int col = n0 + wn * (8 * C::NT) + nt * 8 + ((lane & 3) << 1);
        #pragma unroll
        for (int h = 0; h < 2; h++) {
            int rr = m0 + wm * 32 + mt * 16 + (lane >> 2) + h * 8;
            float v0 = acc[mt][nt][h*2+0], v1 = acc[mt][nt][h*2+1];
            if (bias) { v0 += bias[col]; v1 += bias[col+1]; }
            if (act) {
                v0 = 0.5f * v0 * (1.0f + erff(v0 * 0.70710678118654752f));
                v1 = 0.5f * v1 * (1.0f + erff(v1 * 0.70710678118654752f));
            }
            if (SM == 1) {
                int n = dirmap(kdir, rr);
                long o = ((long)((bz & 3) * NN + n)) * (4 * D_MODEL) + kdir * D_MODEL + col;
                __nv_bfloat162 hv, lv;
                split_hl(v0, hv.x, lv.x); split_hl(v1, hv.y, lv.y);
                *(__nv_bfloat162*)(oh + o) = hv;
                *(__nv_bfloat162*)(ol + o) = lv;
            } else if (outF) {
                *(float2*)(outF + (long)bz * sC + (long)rr * N + col) = make_float2(v0, v1);
            } else {
                long o = (long)rr * N + col;
                __nv_bfloat162 hv, lv;
                split_hl(v0, hv.x, lv.x); split_hl(v1, hv.y, lv.y);
                *(__nv_bfloat162*)(oh + o) = hv;
                *(__nv_bfloat162*)(ol + o) = lv;
            }
        }
    }
}

// ---------------- fp32 SIMT GEMM (x-proj, N=44 only) ----------------
__global__ __launch_bounds__(256) void gemm_abt(
    const float* __restrict__ A, const float* __restrict__ Bw,
    float* __restrict__ C, int M, int N, int K, long sA, long sB, long sC, int bdiv)
{
    int bz = blockIdx.z;
    const float* Ab = A + (long)bz * sA;
    const float* Bb = Bw + (long)(bz / bdiv) * sB;
    float* Cb = C + (long)bz * sC;
    __shared__ float As[16][64];
    __shared__ float Bs[16][64];
    int t = threadIdx.x;
    int tr = t >> 4, tc = t & 15;
    int m0 = blockIdx.y << 6, n0 = blockIdx.x << 6;
    int lm = t >> 2, lk = (t & 3) << 2;
    float acc[4][4] = {};
    int nK = K >> 4;
    for (int kb = 0; kb < nK; kb++) {
        int k0 = kb << 4;
        float4 av = make_float4(0.f,0.f,0.f,0.f), bv = make_float4(0.f,0.f,0.f,0.f);
        if (m0 + lm < M) av = *(const float4*)(Ab + (long)(m0 + lm) * K + k0 + lk);
        if (n0 + lm < N) bv = *(const float4*)(Bb + (long)(n0 + lm) * K + k0 + lk);
        __syncthreads();
        As[lk+0][lm]=av.x; As[lk+1][lm]=av.y; As[lk+2][lm]=av.z; As[lk+3][lm]=av.w;
        Bs[lk+0][lm]=bv.x; Bs[lk+1][lm]=bv.y; Bs[lk+2][lm]=bv.z; Bs[lk+3][lm]=bv.w;
        __syncthreads();
        #pragma unroll
        for (int kk = 0; kk < 16; kk++) {
            float4 a4 = *(const float4*)&As[kk][tr << 2];
            float4 b4 = *(const float4*)&Bs[kk][tc << 2];
            float ar[4] = {a4.x,a4.y,a4.z,a4.w}, br[4] = {b4.x,b4.y,b4.z,b4.w};
            #pragma unroll
            for (int i = 0; i < 4; i++)
                #pragma unroll
                for (int j = 0; j < 4; j++) acc[i][j] += ar[i] * br[j];
        }
    }
    #pragma unroll
    for (int i = 0; i < 4; i++) {
        int m = m0 + (tr << 2) + i;
        if (m >= M) continue;
        #pragma unroll
        for (int j = 0; j < 4; j++) {
            int n = n0 + (tc << 2) + j;
            if (n >= N) continue;
            Cb[(long)m * N + n] = acc[i][j];
        }
    }
}

// ---------------- weight fp32 -> hi/lo ----------------
struct Seg { const float* s; bf16* h; bf16* l; int n; };
struct Segs { Seg a[6]; };
__global__ void wconv(Segs P) {
    Seg sg = P.a[blockIdx.y];
    int i = blockIdx.x * 256 + threadIdx.x;
    if (i < sg.n) { bf16 h, l; split_hl(sg.s[i], h, l); sg.h[i] = h; sg.l[i] = l; }
}

// ---------------- LN in ----------------
__global__ void ln_in_kernel(const float* __restrict__ x,
                             const float* __restrict__ g,
                             const float* __restrict__ b,
                             float* __restrict__ XS,
                             bf16* __restrict__ XSh, bf16* __restrict__ XSl) {
    int row = blockIdx.x;
    int bb = row >> 10, n = row & 1023;
    int c = threadIdx.x;
    float v = x[((long)bb * D_MODEL + c) * NN + n];
    float s = v, s2 = v * v;
    block_reduce2_192(s, s2);
    float mean = s * (1.0f / D_MODEL);
    float var = s2 * (1.0f / D_MODEL) - mean * mean;
    float rstd = rsqrtf(var + 1e-5f);
    float r = (v - mean) * rstd * g[c] + b[c];
    long o = (long)row * D_MODEL + c;
    XS[o] = r;
    bf16 h, l; split_hl(r, h, l);
    XSh[o] = h; XSl[o] = l;
}

// ---------------- conv + silu (x4 vectorized over d) ----------------
__global__ void conv_silu_kernel(const float* __restrict__ XZ,
                                 const float* __restrict__ cw,
                                 const float* __restrict__ cb,
                                 float* __restrict__ XSM) {
    long i4 = (long)blockIdx.x * blockDim.x + threadIdx.x;
    int d4 = (int)(i4 % (D_INNER / 4)) * 4;
    long rt = i4 / (D_INNER / 4);
    int t = (int)(rt & 1023);
    int gp = (int)(rt >> 10);
    int k = gp >> 2;
    float4 acc = *(const float4*)(cb + (long)k * D_INNER + d4);
    float4 wv[4];
    #pragma unroll
    for (int c = 0; c < 4; c++)
        wv[c] = *(const float4*)(cw + ((long)k * D_INNER + d4 + c) * D_CONV);
    const float* base = XZ + ((long)gp * NN) * (2 * D_INNER) + d4;
    #pragma unroll
    for (int j = 0; j < 4; j++) {
        int tau = t - 3 + j;
        if (tau >= 0) {
            float4 xv = *(const float4*)(base + (long)tau * (2 * D_INNER));
            float wj0 = (&wv[0].x)[j], wj1 = (&wv[1].x)[j];
            float wj2 = (&wv[2].x)[j], wj3 = (&wv[3].x)[j];
            acc.x += wj0 * xv.x; acc.y += wj1 * xv.y;
            acc.z += wj2 * xv.z; acc.w += wj3 * xv.w;
        }
    }
    float4 o;
    o.x = siluf(acc.x); o.y = siluf(acc.y); o.z = siluf(acc.z); o.w = siluf(acc.w);
    *(float4*)(XSM + rt * D_INNER + d4) = o;
}

// ---------------- dt projection + softplus (x2 over d) ----------
__global__ void dt_kernel(const float* __restrict__ DBL,
                          const float* __restrict__ wdt,
                          const float* __restrict__ bdt,
                          float* __restrict__ DT) {
    long i2 = (long)blockIdx.x * blockDim.x + threadIdx.x;
    int d2 = (int)(i2 % (D_INNER / 2)) * 2;
    long rt = i2 / (D_INNER / 2);
    int gp = (int)(rt >> 10);
    int k = gp >> 2;
    float4 r0 = *(const float4*)(DBL + rt * DBL_W);
    float4 r1 = *(const float4*)(DBL + rt * DBL_W + 4);
    float4 r2 = *(const float4*)(DBL + rt * DBL_W + 8);
    float2 bb = *(const float2*)(bdt + (long)k * D_INNER + d2);
    float s0 = bb.x, s1 = bb.y;
    const float* w0 = wdt + ((long)k * D_INNER + d2) * DT_RANK;
    const float* w1 = w0 + DT_RANK;
    #pragma unroll
    for (int i = 0; i < 3; i++) {
        float4 w0v = *(const float4*)(w0 + i * 4);
        float4 w1v = *(const float4*)(w1 + i * 4);
        const float4 rv = (i == 0) ? r0 : (i == 1) ? r1 : r2;
        s0 += rv.x * w0v.x + rv.y * w0v.y + rv.z * w0v.z + rv.w * w0v.w;
        s1 += rv.x * w1v.x + rv.y * w1v.y + rv.z * w1v.z + rv.w * w1v.w;
    }
    float d0 = (s0 > 20.0f) ? s0 : log1pf(expf(s0));
    float d1 = (s1 > 20.0f) ? s1 : log1pf(expf(s1));
    *(float2*)(DT + rt * D_INNER + d2) = make_float2(d0, d1);
}

// ---------------- selective scan (proven shape: writes fp32 Y) ----------
__global__ void scan_kernel(const float* __restrict__ DT,
                            const float* __restrict__ XSM,
                            const float* __restrict__ DBL,
                            const float* __restrict__ Alog,
                            float* __restrict__ Y) {
    int gp = blockIdx.z;
    int k = gp >> 2;
    int lane = threadIdx.x & 15;
    int d = (blockIdx.x << 3) + (threadIdx.x >> 4);
    float A = -expf(Alog[((long)k * D_INNER + d) * D_STATE + lane]);
    const float* dtp = DT  + ((long)gp * NN) * D_INNER + d;
    const float* xp_ = XSM + ((long)gp * NN) * D_INNER + d;
    const float* bp  = DBL + ((long)gp * NN) * DBL_W + DT_RANK + lane;
    const float* cp  = bp + D_STATE;
    float* yp = Y + ((long)gp * NN) * D_INNER + d;
    float h = 0.f;
    for (int t = 0; t < NN; t++) {
        float dt = dtp[(long)t * D_INNER];
        float xv = xp_[(long)t * D_INNER];
        float Bv = bp[(long)t * DBL_W];
        float Cv = cp[(long)t * DBL_W];
        float dA = __expf(dt * A);
        h = dA * h + (dt * xv) * Bv;
        float p = h * Cv;
        p += __shfl_xor_sync(0xffffffffu, p, 1);
        p += __shfl_xor_sync(0xffffffffu, p, 2);
        p += __shfl_xor_sync(0xffffffffu, p, 4);
        p += __shfl_xor_sync(0xffffffffu, p, 8);
        if (lane == 0) yp[(long)t * D_INNER] = p;
    }
}

// ---------------- combine (x4 vectorized) ----------------
__global__ void combine_kernel(const float* __restrict__ Y,
                               const float* __restrict__ XSM,
                               const float* __restrict__ XZ,
                               const float* __restrict__ Dp,
                               bf16* __restrict__ YGh, bf16* __restrict__ YGl) {
    long i4 = (long)blockIdx.x * blockDim.x + threadIdx.x;
    long idx = i4 * 4;
    int d = (int)(idx % D_INNER);
    long rt = idx / D_INNER;
    int gp = (int)(rt >> 10);
    int k = gp >> 2;
    float4 z4 = *(const float4*)(XZ + rt * (2 * D_INNER) + D_INNER + d);
    float4 y4 = *(const float4*)(Y + idx);
    float4 x4 = *(const float4*)(XSM + idx);
    float4 D4 = *(const float4*)(Dp + (long)k * D_INNER + d);
    float v0 = (y4.x + x4.x * D4.x) * siluf(z4.x);
    float v1 = (y4.y + x4.y * D4.y) * siluf(z4.y);
    float v2 = (y4.z + x4.z * D4.z) * siluf(z4.z);
    float v3 = (y4.w + x4.w * D4.w) * siluf(z4.w);
    __nv_bfloat162 h0, l0, h1, l1;
    split_hl(v0, h0.x, l0.x); split_hl(v1, h0.y, l0.y);
    split_hl(v2, h1.x, l1.x); split_hl(v3, h1.y, l1.y);
    *(__nv_bfloat162*)(YGh + idx)     = h0;
    *(__nv_bfloat162*)(YGh + idx + 2) = h1;
    *(__nv_bfloat162*)(YGl + idx)     = l0;
    *(__nv_bfloat162*)(YGl + idx + 2) = l1;
}

// ---------------- LN out + residual + transpose ----------------
__global__ void ln_out_kernel(const float* __restrict__ H3,
                              const float* __restrict__ g,
                              const float* __restrict__ b,
                              const float* __restrict__ XS,
                              float* __restrict__ out) {
    int row = blockIdx.x;
    int bb = row >> 10, n = row & 1023;
    int c = threadIdx.x;
    float v = H3[(long)row * D_MODEL + c];
    float s = v, s2 = v * v;
    block_reduce2_192(s, s2);
    float mean = s * (1.0f / D_MODEL);
    float var = s2 * (1.0f / D_MODEL) - mean * mean;
    float rstd = rsqrtf(var + 1e-5f);
    float r = (v - mean) * rstd * g[c] + b[c] + XS[(long)row * D_MODEL + c];
    out[((long)bb * D_MODEL + c) * NN + n] = r;
}

// ---------------- host ----------------
extern "C" void kernel_launch(void* const* d_in, const int* in_sizes, int n_in,
                              void* d_out, int out_size) {
    const float* x      = (const float*)d_in[0];
    const float* norm_g = (const float*)d_in[1];
    const float* norm_b = (const float*)d_in[2];
    const float* in_w   = (const float*)d_in[3];
    const float* in_b   = (const float*)d_in[4];
    const float* m_in_w = (const float*)d_in[5];
    const float* m_cw   = (const float*)d_in[6];
    const float* m_cb   = (const float*)d_in[7];
    const float* m_xp_w = (const float*)d_in[8];
    const float* m_dt_w = (const float*)d_in[9];
    const float* m_dt_b = (const float*)d_in[10];
    const float* m_Alog = (const float*)d_in[11];
    const float* m_D    = (const float*)d_in[12];
    const float* m_out_w= (const float*)d_in[13];
    const float* f_w1   = (const float*)d_in[14];
    const float* f_b1   = (const float*)d_in[15];
    const float* f_w2   = (const float*)d_in[16];
    const float* f_b2   = (const float*)d_in[17];
    const float* o_w    = (const float*)d_in[18];
    const float* o_b    = (const float*)d_in[19];
    const float* on_g   = (const float*)d_in[20];
    const float* on_b   = (const float*)d_in[21];
    float* out = (float*)d_out;

    float *XS, *XZ, *XSM, *DBL, *DT, *Y, *H3;
    cudaGetSymbolAddress((void**)&XS,  g_XS);
    cudaGetSymbolAddress((void**)&XZ,  g_XZ);
    cudaGetSymbolAddress((void**)&XSM, g_XSM);
    cudaGetSymbolAddress((void**)&DBL, g_DBL);
    cudaGetSymbolAddress((void**)&DT,  g_DT);
    cudaGetSymbolAddress((void**)&Y,   g_Y);
    cudaGetSymbolAddress((void**)&H3,  g_H3);

    bf16 *winh,*winl,*wminh,*wminl,*wmoh,*wmol,*wf1h,*wf1l,*wf2h,*wf2l,*woh,*wol;
    bf16 *XSh,*XSl,*XPh,*XPl,*YGh,*YGl,*FUSh,*FUSl,*H1h,*H1l,*H2h,*H2l;
    cudaGetSymbolAddress((void**)&winh, g_win_h);  cudaGetSymbolAddress((void**)&winl, g_win_l);
    cudaGetSymbolAddress((void**)&wminh,g_wmin_h); cudaGetSymbolAddress((void**)&wminl,g_wmin_l);
    cudaGetSymbolAddress((void**)&wmoh, g_wmo_h);  cudaGetSymbolAddress((void**)&wmol, g_wmo_l);
    cudaGetSymbolAddress((void**)&wf1h, g_wf1_h);  cudaGetSymbolAddress((void**)&wf1l, g_wf1_l);
    cudaGetSymbolAddress((void**)&wf2h, g_wf2_h);  cudaGetSymbolAddress((void**)&wf2l, g_wf2_l);
    cudaGetSymbolAddress((void**)&woh,  g_wo_h);   cudaGetSymbolAddress((void**)&wol,  g_wo_l);
    cudaGetSymbolAddress((void**)&XSh,  g_XSh);    cudaGetSymbolAddress((void**)&XSl,  g_XSl);
    cudaGetSymbolAddress((void**)&XPh,  g_XPh);    cudaGetSymbolAddress((void**)&XPl,  g_XPl);
    cudaGetSymbolAddress((void**)&YGh,  g_YGh);    cudaGetSymbolAddress((void**)&YGl,  g_YGl);
    cudaGetSymbolAddress((void**)&FUSh, g_FUSh);   cudaGetSymbolAddress((void**)&FUSl, g_FUSl);
    cudaGetSymbolAddress((void**)&H1h,  g_H1h);    cudaGetSymbolAddress((void**)&H1l,  g_H1l);
    cudaGetSymbolAddress((void**)&H2h,  g_H2h);    cudaGetSymbolAddress((void**)&H2l,  g_H2l);

    cudaFuncSetAttribute(gemm_mma<1,0,128>, cudaFuncAttributeMaxDynamicSharedMemorySize, GCfg<128>::SMEM);
    cudaFuncSetAttribute(gemm_mma<0,1,128>, cudaFuncAttributeMaxDynamicSharedMemorySize, GCfg<128>::SMEM);
    cudaFuncSetAttribute(gemm_mma<0,0,64>,  cudaFuncAttributeMaxDynamicSharedMemorySize, GCfg<64>::SMEM);

    Segs segs;
    segs.a[0] = { in_w,    winh,  winl,  D_MODEL*D_MODEL };
    segs.a[1] = { m_in_w,  wminh, wminl, 4*2*D_INNER*D_MODEL };
    segs.a[2] = { m_out_w, wmoh,  wmol,  4*D_MODEL*D_INNER };
    segs.a[3] = { f_w1,    wf1h,  wf1l,  2*D_MODEL*4*D_MODEL };
    segs.a[4] = { f_w2,    wf2h,  wf2l,  D_MODEL*2*D_MODEL };
    segs.a[5] = { o_w,     woh,   wol,   D_MODEL*D_MODEL };
    wconv<<<dim3(2304, 6, 1), 256>>>(segs);

    ln_in_kernel<<<ROWS, D_MODEL>>>(x, norm_g, norm_b, XS, XSh, XSl);

    // XP = XS @ in_w^T + in_b   (BM=64: 192 CTAs, 4 CTAs/SM)
    gemm_mma<0,0,64><<<dim3(3, 64, 1), 256, GCfg<64>::SMEM>>>(XSh, XSl, winh, winl, in_b,
        nullptr, XPh, XPl, ROWS, D_MODEL, D_MODEL, 0, 0, 0, 1, 0);

    // XZ = gather(XP) @ m_in_w^T  (BM=128: 1536 CTAs, well filled)
    gemm_mma<1,0,128><<<dim3(12, 8, 16), 256, GCfg<128>::SMEM>>>(XPh, XPl, wminh, wminl, nullptr,
        XZ, nullptr, nullptr, NN, 2*D_INNER, D_MODEL,
        0, (long)2*D_INNER*D_MODEL, (long)NN*2*D_INNER, 4, 0);

    conv_silu_kernel<<<(NPAIR*NN*(D_INNER/4))/256, 256>>>(XZ, m_cw, m_cb, XSM);

    gemm_abt<<<dim3(1, 16, 16), 256>>>(XSM, m_xp_w, DBL, NN, DBL_W, D_INNER,
        (long)NN*D_INNER, (long)DBL_W*D_INNER, (long)NN*DBL_W, 4);

    dt_kernel<<<(NPAIR*NN*(D_INNER/2))/256, 256>>>(DBL, m_dt_w, m_dt_b, DT);

    scan_kernel<<<dim3(D_INNER/8, 1, NPAIR), 128>>>(DT, XSM, DBL, m_Alog, Y);

    combine_kernel<<<(NPAIR*NN*(D_INNER/4))/256, 256>>>(Y, XSM, XZ, m_D, YGh, YGl);

    // FUS scatter GEMM (BM=128: 384 CTAs)
    gemm_mma<0,1,128><<<dim3(3, 8, 16), 256, GCfg<128>::SMEM>>>(YGh, YGl, wmoh, wmol, nullptr,
        nullptr, FUSh, FUSl, NN, D_MODEL, D_INNER,
        (long)NN*D_INNER, (long)D_MODEL*D_INNER, 0, 4, 0);

    // MLP1 (BM=64: 384 CTAs vs 192)
    gemm_mma<0,0,64><<<dim3(6, 64, 1), 256, GCfg<64>::SMEM>>>(FUSh, FUSl, wf1h, wf1l, f_b1,
        nullptr, H1h, H1l, ROWS, 2*D_MODEL, 4*D_MODEL, 0, 0, 0, 1, 1);

    // MLP2 (BM=64: 192 CTAs)
    gemm_mma<0,0,64><<<dim3(3, 64, 1), 256, GCfg<64>::SMEM>>>(H1h, H1l, wf2h, wf2l, f_b2,
        nullptr, H2h, H2l, ROWS, D_MODEL, 2*D_MODEL, 0, 0, 0, 1, 0);

    // out-proj (BM=64: 192 CTAs)
    gemm_mma<0,0,64><<<dim3(3, 64, 1), 256, GCfg<64>::SMEM>>>(H2h, H2l, woh, wol, o_b,
        H3, nullptr, nullptr, ROWS, D_MODEL, D_MODEL, 0, 0, 0, 1, 0);

    ln_out_kernel<<<ROWS, D_MODEL>>>(H3, on_g, on_b, XS, out);
}

// round 16
// speedup vs baseline: 1.3824x; 1.0316x over previous
#include <cuda_runtime.h>
#include <cuda_bf16.h>
#include <math.h>

typedef __nv_bfloat16 bf16;

#define D_MODEL 192
#define D_STATE 16
#define D_CONV  4
#define D_INNER 384
#define DT_RANK 12
#define BB      4
#define NN      1024
#define NPAIR   16
#define ROWS    (BB*NN)
#define DBL_W   (DT_RANK + 2*D_STATE)

// ---------------- scratch ----------------
__device__ float g_XS [ROWS * D_MODEL];
__device__ float g_XZ [NPAIR * NN * 2 * D_INNER];
__device__ float g_XSM[NPAIR * NN * D_INNER];
__device__ float g_DBL[NPAIR * NN * DBL_W];
__device__ float g_DD [NPAIR * NN * D_INNER * 2];   // interleaved (dt, dt*x)
__device__ float g_Y  [NPAIR * NN * D_INNER];
__device__ float g_H3 [ROWS * D_MODEL];

__device__ bf16 g_win_h [D_MODEL*D_MODEL],     g_win_l [D_MODEL*D_MODEL];
__device__ bf16 g_wmin_h[4*2*D_INNER*D_MODEL], g_wmin_l[4*2*D_INNER*D_MODEL];
__device__ bf16 g_wmo_h [4*D_MODEL*D_INNER],   g_wmo_l [4*D_MODEL*D_INNER];
__device__ bf16 g_wf1_h [2*D_MODEL*4*D_MODEL], g_wf1_l [2*D_MODEL*4*D_MODEL];
__device__ bf16 g_wf2_h [D_MODEL*2*D_MODEL],   g_wf2_l [D_MODEL*2*D_MODEL];
__device__ bf16 g_wo_h  [D_MODEL*D_MODEL],     g_wo_l  [D_MODEL*D_MODEL];
__device__ bf16 g_XSh [ROWS*D_MODEL],     g_XSl [ROWS*D_MODEL];
__device__ bf16 g_XPh [ROWS*D_MODEL],     g_XPl [ROWS*D_MODEL];
__device__ bf16 g_YGh [NPAIR*NN*D_INNER], g_YGl [NPAIR*NN*D_INNER];
__device__ bf16 g_FUSh[ROWS*4*D_MODEL],   g_FUSl[ROWS*4*D_MODEL];
__device__ bf16 g_H1h [ROWS*2*D_MODEL],   g_H1l [ROWS*2*D_MODEL];
__device__ bf16 g_H2h [ROWS*D_MODEL],     g_H2l [ROWS*D_MODEL];

// ---------------- helpers ----------------
__device__ __forceinline__ float siluf(float x) { return x / (1.0f + expf(-x)); }

__device__ __forceinline__ int dirmap(int k, int t) {
    if (k == 0) return t;
    if (k == 1) return 1023 - t;
    if (k == 2) return ((t & 31) << 5) | (t >> 5);
    int tt = 1023 - t;
    return ((tt & 31) << 5) | (tt >> 5);
}

__device__ __forceinline__ void split_hl(float v, bf16& h, bf16& l) {
    h = __float2bfloat16(v);
    l = __float2bfloat16(v - __bfloat162float(h));
}

__device__ __forceinline__ void block_reduce2_192(float& a, float& b) {
    #pragma unroll
    for (int o = 16; o > 0; o >>= 1) {
        a += __shfl_xor_sync(0xffffffffu, a, o);
        b += __shfl_xor_sync(0xffffffffu, b, o);
    }
    __shared__ float sa[6], sb[6];
    int w = threadIdx.x >> 5, l = threadIdx.x & 31;
    if (l == 0) { sa[w] = a; sb[w] = b; }
    __syncthreads();
    if (threadIdx.x == 0) {
        float ta = 0.f, tb = 0.f;
        #pragma unroll
        for (int i = 0; i < 6; i++) { ta += sa[i]; tb += sb[i]; }
        sa[0] = ta; sb[0] = tb;
    }
    __syncthreads();
    a = sa[0]; b = sb[0];
}

__device__ __forceinline__ void ldsm4(unsigned& r0, unsigned& r1, unsigned& r2, unsigned& r3, unsigned addr) {
    asm volatile("ldmatrix.sync.aligned.m8n8.x4.shared.b16 {%0,%1,%2,%3}, [%4];"
                 : "=r"(r0), "=r"(r1), "=r"(r2), "=r"(r3) : "r"(addr));
}
__device__ __forceinline__ void mma16816(float* c, const unsigned* a, const unsigned* b) {
    asm volatile("mma.sync.aligned.m16n8k16.row.col.f32.bf16.bf16.f32 "
                 "{%0,%1,%2,%3}, {%4,%5,%6,%7}, {%8,%9}, {%0,%1,%2,%3};"
                 : "+f"(c[0]), "+f"(c[1]), "+f"(c[2]), "+f"(c[3])
                 : "r"(a[0]), "r"(a[1]), "r"(a[2]), "r"(a[3]), "r"(b[0]), "r"(b[1]));
}
__device__ __forceinline__ void cpasync16(unsigned dst, const void* src) {
    asm volatile("cp.async.cg.shared.global [%0], [%1], 16;\n" :: "r"(dst), "l"(src));
}
__device__ __forceinline__ void cp_commit() { asm volatile("cp.async.commit_group;\n" ::); }
__device__ __forceinline__ void cp_wait0()  { asm volatile("cp.async.wait_group 0;\n" ::); }

// ---------------- bf16 split tensor GEMM (2-stage, combined 3-product) ------
#define P_PITCH 40

template<int TM> struct GCfg {
    static const int NWM = TM / 32;
    static const int NT  = NWM;
    static const int NB2 = NT / 2 ? NT / 2 : 1;
    static const int AU  = TM / 64;
    static const int AHOFF = 0;
    static const int ALOFF = TM * P_PITCH * 2;
    static const int BHOFF = 2 * TM * P_PITCH * 2;
    static const int BLOFF = BHOFF + 64 * P_PITCH * 2;
    static const int STG   = BLOFF + 64 * P_PITCH * 2;
    static const int SMEM  = 2 * STG;
    static const int OCC   = (TM == 64) ? 4 : 3;
};

template<int DM, int SM, int TM>
__global__ __launch_bounds__(256, GCfg<TM>::OCC) void gemm_mma(
    const bf16* __restrict__ Ah, const bf16* __restrict__ Al,
    const bf16* __restrict__ Bh, const bf16* __restrict__ Bl,
    const float* __restrict__ bias,
    float* __restrict__ outF, bf16* __restrict__ oh, bf16* __restrict__ ol,
    int M, int N, int K, long sA, long sB, long sC, int bdiv, int act)
{
    typedef GCfg<TM> C;
    extern __shared__ char dynsmem[];
    const unsigned smem0 = (unsigned)__cvta_generic_to_shared(dynsmem);

    const int t = threadIdx.x, lane = t & 31, w = t >> 5;
    const int wm = w & (C::NWM - 1), wn = w / C::NWM;
    const int m0 = blockIdx.y * TM, n0 = blockIdx.x * 64;
    const int bz = blockIdx.z;
    const int kdir = bz >> 2;

    const bf16 *Abh, *Abl;
    if (DM == 1) { long o = (long)(bz & 3) * NN * K; Abh = Ah + o; Abl = Al + o; }
    else         { Abh = Ah + (long)bz * sA; Abl = Al + (long)bz * sA; }
    const bf16* Bbh = Bh + (long)(bz / bdiv) * sB;
    const bf16* Bbl = Bl + (long)(bz / bdiv) * sB;

    long aoff[C::AU]; unsigned aswb[C::AU];
    #pragma unroll
    for (int i = 0; i < C::AU; i++) {
        int u = t + i * 256, r = u >> 2, cu = u & 3;
        int rg = m0 + r;
        if (DM == 1) rg = dirmap(kdir, rg);
        aoff[i] = (long)rg * K + cu * 8;
        aswb[i] = (unsigned)((r * P_PITCH + cu * 8) * 2);
    }
    long boff; unsigned bswb;
    { int r = t >> 2, cu = t & 3;
      boff = (long)(n0 + r) * K + cu * 8;
      bswb = (unsigned)((r * P_PITCH + cu * 8) * 2); }

    const int KT = K >> 5;

    int arow[2], brow[C::NB2];
    #pragma unroll
    for (int mt = 0; mt < 2; mt++)
        arow[mt] = (wm * 32 + mt * 16 + (lane & 15)) * P_PITCH + ((lane >> 4) << 3);
    #pragma unroll
    for (int b2 = 0; b2 < C::NB2; b2++)
        brow[b2] = (wn * (8 * C::NT) + b2 * 16 + (lane & 15)) * P_PITCH + ((lane >> 4) << 3);

    float acc[2][C::NT][4];
    #pragma unroll
    for (int i = 0; i < 2; i++)
        #pragma unroll
        for (int j = 0; j < C::NT; j++)
            #pragma unroll
            for (int q = 0; q < 4; q++) acc[i][j][q] = 0.f;

    auto issue = [&](int stg, int kt) {
        int k0 = kt << 5;
        unsigned sb = smem0 + (unsigned)(stg * C::STG);
        #pragma unroll
        for (int i = 0; i < C::AU; i++) {
            cpasync16(sb + C::AHOFF + aswb[i], Abh + aoff[i] + k0);
            cpasync16(sb + C::ALOFF + aswb[i], Abl + aoff[i] + k0);
        }
        cpasync16(sb + C::BHOFF + bswb, Bbh + boff + k0);
        cpasync16(sb + C::BLOFF + bswb, Bbl + boff + k0);
    };

    issue(0, 0); cp_commit();

    for (int it = 0; it < KT; it++) {
        cp_wait0();
        __syncthreads();
        if (it + 1 < KT) { issue((it + 1) & 1, it + 1); cp_commit(); }
        unsigned base = smem0 + (unsigned)((it & 1) * C::STG);
        #pragma unroll
        for (int ks = 0; ks < 2; ks++) {
            unsigned ah[2][4], al[2][4], bh2[C::NT][2], bl2[C::NT][2];
            #pragma unroll
            for (int mt = 0; mt < 2; mt++)
                ldsm4(ah[mt][0], ah[mt][1], ah[mt][2], ah[mt][3],
                      base + C::AHOFF + (unsigned)((arow[mt] + ks * 16) * 2));
            #pragma unroll
            for (int b2 = 0; b2 < C::NB2; b2++) {
                unsigned r0, r1, r2, r3;
                ldsm4(r0, r1, r2, r3, base + C::BHOFF + (unsigned)((brow[b2] + ks * 16) * 2));
                bh2[b2*2][0] = r0; bh2[b2*2+1][0] = r1;
                bh2[b2*2][1] = r2; bh2[b2*2+1][1] = r3;
            }
            #pragma unroll
            for (int mt = 0; mt < 2; mt++)
                #pragma unroll
                for (int nt = 0; nt < C::NT; nt++)
                    mma16816(acc[mt][nt], ah[mt], bh2[nt]);
            #pragma unroll
            for (int b2 = 0; b2 < C::NB2; b2++) {
                unsigned r0, r1, r2, r3;
                ldsm4(r0, r1, r2, r3, base + C::BLOFF + (unsigned)((brow[b2] + ks * 16) * 2));
                bl2[b2*2][0] = r0; bl2[b2*2+1][0] = r1;
                bl2[b2*2][1] = r2; bl2[b2*2+1][1] = r3;
            }
            #pragma unroll
            for (int mt = 0; mt < 2; mt++)
                #pragma unroll
                for (int nt = 0; nt < C::NT; nt++)
                    mma16816(acc[mt][nt], ah[mt], bl2[nt]);
            #pragma unroll
            for (int mt = 0; mt < 2; mt++)
                ldsm4(al[mt][0], al[mt][1], al[mt][2], al[mt][3],
                      base + C::ALOFF + (unsigned)((arow[mt] + ks * 16) * 2));
            #pragma unroll
            for (int mt = 0; mt < 2; mt++)
                #pragma unroll
                for (int nt = 0; nt < C::NT; nt++)
                    mma16816(acc[mt][nt], al[mt], bh2[nt]);
        }
    }

    #pragma unroll
    for (int mt = 0; mt < 2; mt++)
    #pragma unroll
    for (int nt = 0; nt < C::NT; nt++) {
        int col = n0 + wn * (8 * C::NT) + nt * 8 + ((lane & 3) << 1);
        #pragma unroll
        for (int h = 0; h < 2; h++) {
            int rr = m0 + wm * 32 + mt * 16 + (lane >> 2) + h * 8;
            float v0 = acc[mt][nt][h*2+0], v1 = acc[mt][nt][h*2+1];
            if (bias) { v0 += bias[col]; v1 += bias[col+1]; }
            if (act) {
                v0 = 0.5f * v0 * (1.0f + erff(v0 * 0.70710678118654752f));
                v1 = 0.5f * v1 * (1.0f + erff(v1 * 0.70710678118654752f));
            }
            if (SM == 1) {
                int n = dirmap(kdir, rr);
                long o = ((long)((bz & 3) * NN + n)) * (4 * D_MODEL) + kdir * D_MODEL + col;
                __nv_bfloat162 hv, lv;
                split_hl(v0, hv.x, lv.x); split_hl(v1, hv.y, lv.y);
                *(__nv_bfloat162*)(oh + o) = hv;
                *(__nv_bfloat162*)(ol + o) = lv;
            } else if (outF) {
                *(float2*)(outF + (long)bz * sC + (long)rr * N + col) = make_float2(v0, v1);
            } else {
                long o = (long)rr * N + col;
                __nv_bfloat162 hv, lv;
                split_hl(v0, hv.x, lv.x); split_hl(v1, hv.y, lv.y);
                *(__nv_bfloat162*)(oh + o) = hv;
                *(__nv_bfloat162*)(ol + o) = lv;
            }
        }
    }
}

// ---------------- fp32 SIMT GEMM (x-proj, N=44) with B/C pair interleave ----
// cols 0..11 (dt_low) unchanged; B_s -> col 12+2s, C_s -> col 13+2s
// so each lane's (B_s, C_s) is one aligned float2.
__global__ __launch_bounds__(256) void gemm_abt(
    const float* __restrict__ A, const float* __restrict__ Bw,
    float* __restrict__ C, int M, int N, int K, long sA, long sB, long sC, int bdiv)
{
    int bz = blockIdx.z;
    const float* Ab = A + (long)bz * sA;
    const float* Bb = Bw + (long)(bz / bdiv) * sB;
    float* Cb = C + (long)bz * sC;
    __shared__ float As[16][64];
    __shared__ float Bs[16][64];
    int t = threadIdx.x;
    int tr = t >> 4, tc = t & 15;
    int m0 = blockIdx.y << 6, n0 = blockIdx.x << 6;
    int lm = t >> 2, lk = (t & 3) << 2;
    float acc[4][4] = {};
    int nK = K >> 4;
    for (int kb = 0; kb < nK; kb++) {
        int k0 = kb << 4;
        float4 av = make_float4(0.f,0.f,0.f,0.f), bv = make_float4(0.f,0.f,0.f,0.f);
        if (m0 + lm < M) av = *(const float4*)(Ab + (long)(m0 + lm) * K + k0 + lk);
        if (n0 + lm < N) bv = *(const float4*)(Bb + (long)(n0 + lm) * K + k0 + lk);
        __syncthreads();
        As[lk+0][lm]=av.x; As[lk+1][lm]=av.y; As[lk+2][lm]=av.z; As[lk+3][lm]=av.w;
        Bs[lk+0][lm]=bv.x; Bs[lk+1][lm]=bv.y; Bs[lk+2][lm]=bv.z; Bs[lk+3][lm]=bv.w;
        __syncthreads();
        #pragma unroll
        for (int kk = 0; kk < 16; kk++) {
            float4 a4 = *(const float4*)&As[kk][tr << 2];
            float4 b4 = *(const float4*)&Bs[kk][tc << 2];
            float ar[4] = {a4.x,a4.y,a4.z,a4.w}, br[4] = {b4.x,b4.y,b4.z,b4.w};
            #pragma unroll
            for (int i = 0; i < 4; i++)
                #pragma unroll
                for (int j = 0; j < 4; j++) acc[i][j] += ar[i] * br[j];
        }
    }
    #pragma unroll
    for (int i = 0; i < 4; i++) {
        int m = m0 + (tr << 2) + i;
        if (m >= M) continue;
        #pragma unroll
        for (int j = 0; j < 4; j++) {
            int n = n0 + (tc << 2) + j;
            if (n >= N) continue;
            int nw;
            if (n < 12) nw = n;
            else {
                int s = n - 12;
                nw = (s < 16) ? (12 + 2 * s) : (13 + 2 * (s - 16));
            }
            Cb[(long)m * N + nw] = acc[i][j];
        }
    }
}

// ---------------- weight fp32 -> hi/lo ----------------
struct Seg { const float* s; bf16* h; bf16* l; int n; };
struct Segs { Seg a[6]; };
__global__ void wconv(Segs P) {
    Seg sg = P.a[blockIdx.y];
    int i = blockIdx.x * 256 + threadIdx.x;
    if (i < sg.n) { bf16 h, l; split_hl(sg.s[i], h, l); sg.h[i] = h; sg.l[i] = l; }
}

// ---------------- LN in ----------------
__global__ void ln_in_kernel(const float* __restrict__ x,
                             const float* __restrict__ g,
                             const float* __restrict__ b,
                             float* __restrict__ XS,
                             bf16* __restrict__ XSh, bf16* __restrict__ XSl) {
    int row = blockIdx.x;
    int bb = row >> 10, n = row & 1023;
    int c = threadIdx.x;
    float v = x[((long)bb * D_MODEL + c) * NN + n];
    float s = v, s2 = v * v;
    block_reduce2_192(s, s2);
    float mean = s * (1.0f / D_MODEL);
    float var = s2 * (1.0f / D_MODEL) - mean * mean;
    float rstd = rsqrtf(var + 1e-5f);
    float r = (v - mean) * rstd * g[c] + b[c];
    long o = (long)row * D_MODEL + c;
    XS[o] = r;
    bf16 h, l; split_hl(r, h, l);
    XSh[o] = h; XSl[o] = l;
}

// ---------------- conv + silu (x4 vectorized over d) ----------------
__global__ void conv_silu_kernel(const float* __restrict__ XZ,
                                 const float* __restrict__ cw,
                                 const float* __restrict__ cb,
                                 float* __restrict__ XSM) {
    long i4 = (long)blockIdx.x * blockDim.x + threadIdx.x;
    int d4 = (int)(i4 % (D_INNER / 4)) * 4;
    long rt = i4 / (D_INNER / 4);
    int t = (int)(rt & 1023);
    int gp = (int)(rt >> 10);
    int k = gp >> 2;
    float4 acc = *(const float4*)(cb + (long)k * D_INNER + d4);
    float4 wv[4];
    #pragma unroll
    for (int c = 0; c < 4; c++)
        wv[c] = *(const float4*)(cw + ((long)k * D_INNER + d4 + c) * D_CONV);
    const float* base = XZ + ((long)gp * NN) * (2 * D_INNER) + d4;
    #pragma unroll
    for (int j = 0; j < 4; j++) {
        int tau = t - 3 + j;
        if (tau >= 0) {
            float4 xv = *(const float4*)(base + (long)tau * (2 * D_INNER));
            float wj0 = (&wv[0].x)[j], wj1 = (&wv[1].x)[j];
            float wj2 = (&wv[2].x)[j], wj3 = (&wv[3].x)[j];
            acc.x += wj0 * xv.x; acc.y += wj1 * xv.y;
            acc.z += wj2 * xv.z; acc.w += wj3 * xv.w;
        }
    }
    float4 o;
    o.x = siluf(acc.x); o.y = siluf(acc.y); o.z = siluf(acc.z); o.w = siluf(acc.w);
    *(float4*)(XSM + rt * D_INNER + d4) = o;
}

// ---------------- dt projection + softplus -> interleaved (dt, dt*x) -------
__global__ void dt_kernel(const float* __restrict__ DBL,
                          const float* __restrict__ XSM,
                          const float* __restrict__ wdt,
                          const float* __restrict__ bdt,
                          float* __restrict__ DD) {
    long i2 = (long)blockIdx.x * blockDim.x + threadIdx.x;
    int d2 = (int)(i2 % (D_INNER / 2)) * 2;
    long rt = i2 / (D_INNER / 2);
    int gp = (int)(rt >> 10);
    int k = gp >> 2;
    float4 r0 = *(const float4*)(DBL + rt * DBL_W);
    float4 r1 = *(const float4*)(DBL + rt * DBL_W + 4);
    float4 r2 = *(const float4*)(DBL + rt * DBL_W + 8);
    float2 bb = *(const float2*)(bdt + (long)k * D_INNER + d2);
    float s0 = bb.x, s1 = bb.y;
    const float* w0 = wdt + ((long)k * D_INNER + d2) * DT_RANK;
    const float* w1 = w0 + DT_RANK;
    #pragma unroll
    for (int i = 0; i < 3; i++) {
        float4 w0v = *(const float4*)(w0 + i * 4);
        float4 w1v = *(const float4*)(w1 + i * 4);
        const float4 rv = (i == 0) ? r0 : (i == 1) ? r1 : r2;
        s0 += rv.x * w0v.x + rv.y * w0v.y + rv.z * w0v.z + rv.w * w0v.w;
        s1 += rv.x * w1v.x + rv.y * w1v.y + rv.z * w1v.z + rv.w * w1v.w;
    }
    float d0 = (s0 > 20.0f) ? s0 : log1pf(expf(s0));
    float d1 = (s1 > 20.0f) ? s1 : log1pf(expf(s1));
    float2 xv = *(const float2*)(XSM + rt * D_INNER + d2);
    float4 o = make_float4(d0, d0 * xv.x, d1, d1 * xv.y);
    *(float4*)(DD + rt * (2 * D_INNER) + 2 * d2) = o;
}

// ---------------- selective scan (16 lanes/channel, packed operands) --------
// Per step: LDG.64 (dt,dtx) + LDG.64 (B,C) + MUFU + FFMA chain + 4 SHFL.
__global__ void scan_kernel(const float* __restrict__ DD,
                            const float* __restrict__ DBL,
                            const float* __restrict__ Alog,
                            float* __restrict__ Y) {
    int gp = blockIdx.z;
    int k = gp >> 2;
    int lane = threadIdx.x & 15;
    int d = (blockIdx.x << 3) + (threadIdx.x >> 4);
    float A = -expf(Alog[((long)k * D_INNER + d) * D_STATE + lane]);
    const float* ddp = DD  + ((long)gp * NN) * (2 * D_INNER) + 2 * d;
    const float* bcp = DBL + ((long)gp * NN) * DBL_W + DT_RANK + 2 * lane;
    float* yp = Y + ((long)gp * NN) * D_INNER + d;
    float h = 0.f;
    for (int t = 0; t < NN; t++) {
        float2 dd = *(const float2*)(ddp + (long)t * (2 * D_INNER));
        float2 bc = *(const float2*)(bcp + (long)t * DBL_W);
        float dA = __expf(dd.x * A);
        h = dA * h + dd.y * bc.x;
        float p = h * bc.y;
        p += __shfl_xor_sync(0xffffffffu, p, 1);
        p += __shfl_xor_sync(0xffffffffu, p, 2);
        p += __shfl_xor_sync(0xffffffffu, p, 4);
        p += __shfl_xor_sync(0xffffffffu, p, 8);
        if (lane == 0) yp[(long)t * D_INNER] = p;
    }
}

// ---------------- combine (x4 vectorized) ----------------
__global__ void combine_kernel(const float* __restrict__ Y,
                               const float* __restrict__ XSM,
                               const float* __restrict__ XZ,
                               const float* __restrict__ Dp,
                               bf16* __restrict__ YGh, bf16* __restrict__ YGl) {
    long i4 = (long)blockIdx.x * blockDim.x + threadIdx.x;
    long idx = i4 * 4;
    int d = (int)(idx % D_INNER);
    long rt = idx / D_INNER;
    int gp = (int)(rt >> 10);
    int k = gp >> 2;
    float4 z4 = *(const float4*)(XZ + rt * (2 * D_INNER) + D_INNER + d);
    float4 y4 = *(const float4*)(Y + idx);
    float4 x4 = *(const float4*)(XSM + idx);
    float4 D4 = *(const float4*)(Dp + (long)k * D_INNER + d);
    float v0 = (y4.x + x4.x * D4.x) * siluf(z4.x);
    float v1 = (y4.y + x4.y * D4.y) * siluf(z4.y);
    float v2 = (y4.z + x4.z * D4.z) * siluf(z4.z);
    float v3 = (y4.w + x4.w * D4.w) * siluf(z4.w);
    __nv_bfloat162 h0, l0, h1, l1;
    split_hl(v0, h0.x, l0.x); split_hl(v1, h0.y, l0.y);
    split_hl(v2, h1.x, l1.x); split_hl(v3, h1.y, l1.y);
    *(__nv_bfloat162*)(YGh + idx)     = h0;
    *(__nv_bfloat162*)(YGh + idx + 2) = h1;
    *(__nv_bfloat162*)(YGl + idx)     = l0;
    *(__nv_bfloat162*)(YGl + idx + 2) = l1;
}

// ---------------- LN out + residual + transpose ----------------
__global__ void ln_out_kernel(const float* __restrict__ H3,
                              const float* __restrict__ g,
                              const float* __restrict__ b,
                              const float* __restrict__ XS,
                              float* __restrict__ out) {
    int row = blockIdx.x;
    int bb = row >> 10, n = row & 1023;
    int c = threadIdx.x;
    float v = H3[(long)row * D_MODEL + c];
    float s = v, s2 = v * v;
    block_reduce2_192(s, s2);
    float mean = s * (1.0f / D_MODEL);
    float var = s2 * (1.0f / D_MODEL) - mean * mean;
    float rstd = rsqrtf(var + 1e-5f);
    float r = (v - mean) * rstd * g[c] + b[c] + XS[(long)row * D_MODEL + c];
    out[((long)bb * D_MODEL + c) * NN + n] = r;
}

// ---------------- host ----------------
extern "C" void kernel_launch(void* const* d_in, const int* in_sizes, int n_in,
                              void* d_out, int out_size) {
    const float* x      = (const float*)d_in[0];
    const float* norm_g = (const float*)d_in[1];
    const float* norm_b = (const float*)d_in[2];
    const float* in_w   = (const float*)d_in[3];
    const float* in_b   = (const float*)d_in[4];
    const float* m_in_w = (const float*)d_in[5];
    const float* m_cw   = (const float*)d_in[6];
    const float* m_cb   = (const float*)d_in[7];
    const float* m_xp_w = (const float*)d_in[8];
    const float* m_dt_w = (const float*)d_in[9];
    const float* m_dt_b = (const float*)d_in[10];
    const float* m_Alog = (const float*)d_in[11];
    const float* m_D    = (const float*)d_in[12];
    const float* m_out_w= (const float*)d_in[13];
    const float* f_w1   = (const float*)d_in[14];
    const float* f_b1   = (const float*)d_in[15];
    const float* f_w2   = (const float*)d_in[16];
    const float* f_b2   = (const float*)d_in[17];
    const float* o_w    = (const float*)d_in[18];
    const float* o_b    = (const float*)d_in[19];
    const float* on_g   = (const float*)d_in[20];
    const float* on_b   = (const float*)d_in[21];
    float* out = (float*)d_out;

    float *XS, *XZ, *XSM, *DBL, *DD, *Y, *H3;
    cudaGetSymbolAddress((void**)&XS,  g_XS);
    cudaGetSymbolAddress((void**)&XZ,  g_XZ);
    cudaGetSymbolAddress((void**)&XSM, g_XSM);
    cudaGetSymbolAddress((void**)&DBL, g_DBL);
    cudaGetSymbolAddress((void**)&DD,  g_DD);
    cudaGetSymbolAddress((void**)&Y,   g_Y);
    cudaGetSymbolAddress((void**)&H3,  g_H3);

    bf16 *winh,*winl,*wminh,*wminl,*wmoh,*wmol,*wf1h,*wf1l,*wf2h,*wf2l,*woh,*wol;
    bf16 *XSh,*XSl,*XPh,*XPl,*YGh,*YGl,*FUSh,*FUSl,*H1h,*H1l,*H2h,*H2l;
    cudaGetSymbolAddress((void**)&winh, g_win_h);  cudaGetSymbolAddress((void**)&winl, g_win_l);
    cudaGetSymbolAddress((void**)&wminh,g_wmin_h); cudaGetSymbolAddress((void**)&wminl,g_wmin_l);
    cudaGetSymbolAddress((void**)&wmoh, g_wmo_h);  cudaGetSymbolAddress((void**)&wmol, g_wmo_l);
    cudaGetSymbolAddress((void**)&wf1h, g_wf1_h);  cudaGetSymbolAddress((void**)&wf1l, g_wf1_l);
    cudaGetSymbolAddress((void**)&wf2h, g_wf2_h);  cudaGetSymbolAddress((void**)&wf2l, g_wf2_l);
    cudaGetSymbolAddress((void**)&woh,  g_wo_h);   cudaGetSymbolAddress((void**)&wol,  g_wo_l);
    cudaGetSymbolAddress((void**)&XSh,  g_XSh);    cudaGetSymbolAddress((void**)&XSl,  g_XSl);
    cudaGetSymbolAddress((void**)&XPh,  g_XPh);    cudaGetSymbolAddress((void**)&XPl,  g_XPl);
    cudaGetSymbolAddress((void**)&YGh,  g_YGh);    cudaGetSymbolAddress((void**)&YGl,  g_YGl);
    cudaGetSymbolAddress((void**)&FUSh, g_FUSh);   cudaGetSymbolAddress((void**)&FUSl, g_FUSl);
    cudaGetSymbolAddress((void**)&H1h,  g_H1h);    cudaGetSymbolAddress((void**)&H1l,  g_H1l);
    cudaGetSymbolAddress((void**)&H2h,  g_H2h);    cudaGetSymbolAddress((void**)&H2l,  g_H2l);

    cudaFuncSetAttribute(gemm_mma<1,0,128>, cudaFuncAttributeMaxDynamicSharedMemorySize, GCfg<128>::SMEM);
    cudaFuncSetAttribute(gemm_mma<0,1,128>, cudaFuncAttributeMaxDynamicSharedMemorySize, GCfg<128>::SMEM);
    cudaFuncSetAttribute(gemm_mma<0,0,64>,  cudaFuncAttributeMaxDynamicSharedMemorySize, GCfg<64>::SMEM);

    Segs segs;
    segs.a[0] = { in_w,    winh,  winl,  D_MODEL*D_MODEL };
    segs.a[1] = { m_in_w,  wminh, wminl, 4*2*D_INNER*D_MODEL };
    segs.a[2] = { m_out_w, wmoh,  wmol,  4*D_MODEL*D_INNER };
    segs.a[3] = { f_w1,    wf1h,  wf1l,  2*D_MODEL*4*D_MODEL };
    segs.a[4] = { f_w2,    wf2h,  wf2l,  D_MODEL*2*D_MODEL };
    segs.a[5] = { o_w,     woh,   wol,   D_MODEL*D_MODEL };
    wconv<<<dim3(2304, 6, 1), 256>>>(segs);

    ln_in_kernel<<<ROWS, D_MODEL>>>(x, norm_g, norm_b, XS, XSh, XSl);

    gemm_mma<0,0,64><<<dim3(3, 64, 1), 256, GCfg<64>::SMEM>>>(XSh, XSl, winh, winl, in_b,
        nullptr, XPh, XPl, ROWS, D_MODEL, D_MODEL, 0, 0, 0, 1, 0);

    gemm_mma<1,0,128><<<dim3(12, 8, 16), 256, GCfg<128>::SMEM>>>(XPh, XPl, wminh, wminl, nullptr,
        XZ, nullptr, nullptr, NN, 2*D_INNER, D_MODEL,
        0, (long)2*D_INNER*D_MODEL, (long)NN*2*D_INNER, 4, 0);

    conv_silu_kernel<<<(NPAIR*NN*(D_INNER/4))/256, 256>>>(XZ, m_cw, m_cb, XSM);

    gemm_abt<<<dim3(1, 16, 16), 256>>>(XSM, m_xp_w, DBL, NN, DBL_W, D_INNER,
        (long)NN*D_INNER, (long)DBL_W*D_INNER, (long)NN*DBL_W, 4);

    dt_kernel<<<(NPAIR*NN*(D_INNER/2))/256, 256>>>(DBL, XSM, m_dt_w, m_dt_b, DD);

    scan_kernel<<<dim3(D_INNER/8, 1, NPAIR), 128>>>(DD, DBL, m_Alog, Y);

    combine_kernel<<<(NPAIR*NN*(D_INNER/4))/256, 256>>>(Y, XSM, XZ, m_D, YGh, YGl);

    gemm_mma<0,1,128><<<dim3(3, 8, 16), 256, GCfg<128>::SMEM>>>(YGh, YGl, wmoh, wmol, nullptr,
        nullptr, FUSh, FUSl, NN, D_MODEL, D_INNER,
        (long)NN*D_INNER, (long)D_MODEL*D_INNER, 0, 4, 0);

    gemm_mma<0,0,64><<<dim3(6, 64, 1), 256, GCfg<64>::SMEM>>>(FUSh, FUSl, wf1h, wf1l, f_b1,
        nullptr, H1h, H1l, ROWS, 2*D_MODEL, 4*D_MODEL, 0, 0, 0, 1, 1);

    gemm_mma<0,0,64><<<dim3(3, 64, 1), 256, GCfg<64>::SMEM>>>(H1h, H1l, wf2h, wf2l, f_b2,
        nullptr, H2h, H2l, ROWS, D_MODEL, 2*D_MODEL, 0, 0, 0, 1, 0);

    gemm_mma<0,0,64><<<dim3(3, 64, 1), 256, GCfg<64>::SMEM>>>(H2h, H2l, woh, wol, o_b,
        H3, nullptr, nullptr, ROWS, D_MODEL, D_MODEL, 0, 0, 0, 1, 0);

    ln_out_kernel<<<ROWS, D_MODEL>>>(H3, on_g, on_b, XS, out);
}